// round 1
// baseline (speedup 1.0000x reference)
#include <cuda_runtime.h>

#define NB 32
#define NS 8
#define NHD 8
#define QKIN 8192
#define TKD 512
#define DKH 64
#define KSLICES 16
#define KSLEN 512

// ---- scratch (static __device__ globals; no allocations) ----
__device__ float g_qa[NB * QKIN];                 // pooled inputs   (32, 8192)
__device__ float g_ka[NB * NS * QKIN];            // pooled k_ant    (256, 8192)
__device__ float g_qpart[KSLICES * NB * TKD];     // split-K partials q
__device__ float g_kpart[KSLICES * NB * NS * TKD];// split-K partials k
__device__ float g_q[NB * TKD];                   // q (32, 512)
__device__ float g_k[NB * NS * TKD];              // k (256, 512)
__device__ float g_wgt[NB * NHD * NS];            // softmax weights (32, 8, 8)
__device__ float g_x[NB * 1024 * 128];            // attention output image (32, 32, 32, 128)

__constant__ int c_ridx[8] = {0, 0, 0, 0, 0, 1, 2, 3}; // rel-emb row index

// ---------------- avg pool 4x4 -> flattened (img, 8*8*128) ----------------
__global__ void pool_kernel(const float* __restrict__ in, int nImg, int which) {
    float* out = which ? g_ka : g_qa;
    int idx = blockIdx.x * 256 + threadIdx.x;      // float4 units
    if (idx >= nImg * 2048) return;
    int c4 = idx & 31;
    int pw = (idx >> 5) & 7;
    int ph = (idx >> 8) & 7;
    int img = idx >> 11;
    const float4* p4 = (const float4*)in;
    float sx = 0.f, sy = 0.f, sz = 0.f, sw = 0.f;
#pragma unroll
    for (int i = 0; i < 4; i++)
#pragma unroll
        for (int j = 0; j < 4; j++) {
            float4 v = p4[((img * 32 + ph * 4 + i) * 32 + pw * 4 + j) * 32 + c4];
            sx += v.x; sy += v.y; sz += v.z; sw += v.w;
        }
    ((float4*)out)[idx] = make_float4(sx * 0.0625f, sy * 0.0625f, sz * 0.0625f, sw * 0.0625f);
}

// ---------------- split-K GEMM: C[M,512] = A[M,8192] @ W[8192,512] ----------------
__global__ __launch_bounds__(256) void gemm_splitk(const float* __restrict__ Wm, int which) {
    const float* A = which ? g_ka : g_qa;
    float* part = which ? g_kpart : g_qpart;
    int M = which ? (NB * NS) : NB;
    __shared__ float As[32][33];
    __shared__ float Bs[32][65];
    int nt = blockIdx.x, mt = blockIdx.y, ks = blockIdx.z;
    int t = threadIdx.x;
    int tx = t & 15, ty = t >> 4;
    float acc[2][4] = {};
    int m0 = mt * 32, n0 = nt * 64, kbase = ks * KSLEN;
    for (int kk = 0; kk < KSLEN; kk += 32) {
        int k0 = kbase + kk;
#pragma unroll
        for (int i = 0; i < 4; i++) {
            int e = t + i * 256; int r = e >> 5, c = e & 31;
            As[r][c] = A[(m0 + r) * QKIN + k0 + c];
        }
#pragma unroll
        for (int i = 0; i < 8; i++) {
            int e = t + i * 256; int r = e >> 6, c = e & 63;
            Bs[r][c] = Wm[(k0 + r) * TKD + n0 + c];
        }
        __syncthreads();
#pragma unroll
        for (int k = 0; k < 32; k++) {
            float a0 = As[ty * 2][k], a1 = As[ty * 2 + 1][k];
            float b0 = Bs[k][tx * 4 + 0], b1 = Bs[k][tx * 4 + 1];
            float b2 = Bs[k][tx * 4 + 2], b3 = Bs[k][tx * 4 + 3];
            acc[0][0] = fmaf(a0, b0, acc[0][0]); acc[0][1] = fmaf(a0, b1, acc[0][1]);
            acc[0][2] = fmaf(a0, b2, acc[0][2]); acc[0][3] = fmaf(a0, b3, acc[0][3]);
            acc[1][0] = fmaf(a1, b0, acc[1][0]); acc[1][1] = fmaf(a1, b1, acc[1][1]);
            acc[1][2] = fmaf(a1, b2, acc[1][2]); acc[1][3] = fmaf(a1, b3, acc[1][3]);
        }
        __syncthreads();
    }
#pragma unroll
    for (int r = 0; r < 2; r++)
#pragma unroll
        for (int c = 0; c < 4; c++)
            part[(ks * M + m0 + ty * 2 + r) * TKD + n0 + tx * 4 + c] = acc[r][c];
}

__global__ void reduce_parts(int which) {
    const float* part = which ? g_kpart : g_qpart;
    float* out = which ? g_k : g_q;
    int M = which ? (NB * NS) : NB;
    int idx = blockIdx.x * 256 + threadIdx.x;
    if (idx >= M * TKD) return;
    float s = 0.f;
#pragma unroll
    for (int z = 0; z < KSLICES; z++) s += part[z * M * TKD + idx];
    out[idx] = s;
}

// ---------------- attention weights: logits -> softmax ----------------
__global__ void attn_kernel(const float* __restrict__ tk) {
    int b = blockIdx.x;
    int t = threadIdx.x;
    int h = t >> 5, lane = t & 31;
    float q0 = g_q[b * TKD + h * DKH + lane];
    float q1 = g_q[b * TKD + h * DKH + 32 + lane];
    float lg[8];
#pragma unroll
    for (int s = 0; s < 8; s++) {
        int r = c_ridx[s];
        float k0 = g_k[(b * 8 + s) * TKD + h * DKH + lane] + tk[r * DKH + lane];
        float k1 = g_k[(b * 8 + s) * TKD + h * DKH + 32 + lane] + tk[r * DKH + 32 + lane];
        float p = q0 * k0 + q1 * k1;
#pragma unroll
        for (int off = 16; off; off >>= 1) p += __shfl_xor_sync(0xffffffffu, p, off);
        lg[s] = p * 0.125f;   // q scale 1/sqrt(64), applies to both dot terms
    }
    float m = lg[0];
#pragma unroll
    for (int s = 1; s < 8; s++) m = fmaxf(m, lg[s]);
    float sum = 0.f;
#pragma unroll
    for (int s = 0; s < 8; s++) { lg[s] = expf(lg[s] - m); sum += lg[s]; }
    float inv = 1.f / sum;
    if (lane == 0) {
#pragma unroll
        for (int s = 0; s < 8; s++) g_wgt[b * 64 + h * 8 + s] = lg[s] * inv;
    }
}

// ---------------- fused: weighted-sum over S  +  conv_v 3x3  +  z_v + bias ----------------
// One block per (b, head). Head h owns output rows [4h, 4h+4).
// smem: s_wgt[8] | s_in[6][34][128] (weighted, padded input) | s_w[128][128] (one tap)
__global__ __launch_bounds__(256, 1) void conv_v_kernel(
    const float* __restrict__ v_ant, const float* __restrict__ cw,
    const float* __restrict__ cb, const float* __restrict__ tv) {
    int h = blockIdx.x, b = blockIdx.y;
    extern __shared__ float sm[];
    float* s_wgt = sm;
    float* s_in  = sm + 8;
    float* s_w   = sm + 8 + 6 * 34 * 128;
    int t = threadIdx.x;
    if (t < 8) s_wgt[t] = g_wgt[b * 64 + h * 8 + t];
    __syncthreads();

    // weighted input tile: rows 4h-1..4h+4, cols -1..32, zero padded
    for (int e = t; e < 6 * 34 * 32; e += 256) {
        int c4 = e & 31;
        int ci = (e >> 5) % 34;
        int ri = e / (34 * 32);
        int gr = h * 4 - 1 + ri;
        int gc = ci - 1;
        float ax = 0.f, ay = 0.f, az = 0.f, aw = 0.f;
        if (gr >= 0 && gr < 32 && gc >= 0 && gc < 32) {
            const float4* vp = (const float4*)v_ant;
            int base = (b * 8 * 1024 + gr * 32 + gc) * 32 + c4;
#pragma unroll
            for (int s = 0; s < 8; s++) {
                float4 vv = vp[base + s * 32768];
                float w = s_wgt[s];
                ax = fmaf(w, vv.x, ax); ay = fmaf(w, vv.y, ay);
                az = fmaf(w, vv.z, az); aw = fmaf(w, vv.w, aw);
            }
        }
        *(float4*)&s_in[(ri * 34 + ci) * 128 + c4 * 4] = make_float4(ax, ay, az, aw);
    }

    int tx = t & 15, ty = t >> 4;
    float4 acc0[8], acc1[8];
#pragma unroll
    for (int i = 0; i < 8; i++) { acc0[i] = make_float4(0,0,0,0); acc1[i] = make_float4(0,0,0,0); }
    int sbase[8];
#pragma unroll
    for (int i = 0; i < 8; i++) {
        int p = ty + i * 16;
        sbase[i] = (((p >> 5) + 1) * 34 + (p & 31) + 1) * 128;
    }

    for (int tap = 0; tap < 9; tap++) {
        __syncthreads();
        for (int e = t; e < 16384; e += 256) s_w[e] = cw[tap * 16384 + e];
        __syncthreads();
        int dy = tap / 3 - 1, dx = tap % 3 - 1;
        int doff = (dy * 34 + dx) * 128;
#pragma unroll 2
        for (int cin = 0; cin < 128; cin++) {
            float4 bA = *(const float4*)&s_w[cin * 128 + tx * 8];
            float4 bB = *(const float4*)&s_w[cin * 128 + tx * 8 + 4];
#pragma unroll
            for (int i = 0; i < 8; i++) {
                float a = s_in[sbase[i] + doff + cin];
                acc0[i].x = fmaf(a, bA.x, acc0[i].x);
                acc0[i].y = fmaf(a, bA.y, acc0[i].y);
                acc0[i].z = fmaf(a, bA.z, acc0[i].z);
                acc0[i].w = fmaf(a, bA.w, acc0[i].w);
                acc1[i].x = fmaf(a, bB.x, acc1[i].x);
                acc1[i].y = fmaf(a, bB.y, acc1[i].y);
                acc1[i].z = fmaf(a, bB.z, acc1[i].z);
                acc1[i].w = fmaf(a, bB.w, acc1[i].w);
            }
        }
    }

    // epilogue: + bias + weighted z_v, store image layout
    const float4* cb4 = (const float4*)cb;
    float4 bias0 = cb4[tx * 2], bias1 = cb4[tx * 2 + 1];
#pragma unroll
    for (int i = 0; i < 8; i++) {
        int p = ty + i * 16;
        float r0x = bias0.x, r0y = bias0.y, r0z = bias0.z, r0w = bias0.w;
        float r1x = bias1.x, r1y = bias1.y, r1z = bias1.z, r1w = bias1.w;
#pragma unroll
        for (int s = 0; s < 8; s++) {
            float w = s_wgt[s];
            const float4* tp = (const float4*)&tv[c_ridx[s] * 16384 + p * 128 + tx * 8];
            float4 t0 = tp[0], t1 = tp[1];
            r0x = fmaf(w, t0.x, r0x); r0y = fmaf(w, t0.y, r0y);
            r0z = fmaf(w, t0.z, r0z); r0w = fmaf(w, t0.w, r0w);
            r1x = fmaf(w, t1.x, r1x); r1y = fmaf(w, t1.y, r1y);
            r1z = fmaf(w, t1.z, r1z); r1w = fmaf(w, t1.w, r1w);
        }
        int gr = h * 4 + (p >> 5), gc = p & 31;
        float4* xp = (float4*)&g_x[(b * 1024 + gr * 32 + gc) * 128 + tx * 8];
        xp[0] = make_float4(acc0[i].x + r0x, acc0[i].y + r0y, acc0[i].z + r0z, acc0[i].w + r0w);
        xp[1] = make_float4(acc1[i].x + r1x, acc1[i].y + r1y, acc1[i].z + r1z, acc1[i].w + r1w);
    }
}

// ---------------- conv_o 3x3: (32,32,32,128) -> (32,32,32,64) ----------------
__global__ __launch_bounds__(256, 1) void conv_o_kernel(
    const float* __restrict__ cw, const float* __restrict__ cb, float* __restrict__ out) {
    int rb = blockIdx.x, b = blockIdx.y;
    extern __shared__ float sm[];
    float* s_in = sm;                 // 6*34*128
    float* s_w  = sm + 6 * 34 * 128;  // 128*64
    int t = threadIdx.x;
    for (int e = t; e < 6 * 34 * 32; e += 256) {
        int c4 = e & 31;
        int ci = (e >> 5) % 34;
        int ri = e / (34 * 32);
        int gr = rb * 4 - 1 + ri, gc = ci - 1;
        float4 v = make_float4(0, 0, 0, 0);
        if (gr >= 0 && gr < 32 && gc >= 0 && gc < 32)
            v = *(const float4*)&g_x[(b * 1024 + gr * 32 + gc) * 128 + c4 * 4];
        *(float4*)&s_in[(ri * 34 + ci) * 128 + c4 * 4] = v;
    }
    int tx = t & 7, ty = t >> 3;
    float4 acc0[4], acc1[4];
#pragma unroll
    for (int i = 0; i < 4; i++) { acc0[i] = make_float4(0,0,0,0); acc1[i] = make_float4(0,0,0,0); }
    int sbase[4];
#pragma unroll
    for (int i = 0; i < 4; i++) {
        int p = ty + i * 32;
        sbase[i] = (((p >> 5) + 1) * 34 + (p & 31) + 1) * 128;
    }
    for (int tap = 0; tap < 9; tap++) {
        __syncthreads();
        for (int e = t; e < 8192; e += 256) s_w[e] = cw[tap * 8192 + e];
        __syncthreads();
        int dy = tap / 3 - 1, dx = tap % 3 - 1;
        int doff = (dy * 34 + dx) * 128;
#pragma unroll 2
        for (int cin = 0; cin < 128; cin++) {
            float4 bA = *(const float4*)&s_w[cin * 64 + tx * 8];
            float4 bB = *(const float4*)&s_w[cin * 64 + tx * 8 + 4];
#pragma unroll
            for (int i = 0; i < 4; i++) {
                float a = s_in[sbase[i] + doff + cin];
                acc0[i].x = fmaf(a, bA.x, acc0[i].x);
                acc0[i].y = fmaf(a, bA.y, acc0[i].y);
                acc0[i].z = fmaf(a, bA.z, acc0[i].z);
                acc0[i].w = fmaf(a, bA.w, acc0[i].w);
                acc1[i].x = fmaf(a, bB.x, acc1[i].x);
                acc1[i].y = fmaf(a, bB.y, acc1[i].y);
                acc1[i].z = fmaf(a, bB.z, acc1[i].z);
                acc1[i].w = fmaf(a, bB.w, acc1[i].w);
            }
        }
    }
    const float4* cb4 = (const float4*)cb;
    float4 bias0 = cb4[tx * 2], bias1 = cb4[tx * 2 + 1];
#pragma unroll
    for (int i = 0; i < 4; i++) {
        int p = ty + i * 32;
        int gr = rb * 4 + (p >> 5), gc = p & 31;
        float4* op = (float4*)&out[(b * 1024 + gr * 32 + gc) * 64 + tx * 8];
        op[0] = make_float4(acc0[i].x + bias0.x, acc0[i].y + bias0.y,
                            acc0[i].z + bias0.z, acc0[i].w + bias0.w);
        op[1] = make_float4(acc1[i].x + bias1.x, acc1[i].y + bias1.y,
                            acc1[i].z + bias1.z, acc1[i].w + bias1.w);
    }
}

extern "C" void kernel_launch(void* const* d_in, const int* in_sizes, int n_in,
                              void* d_out, int out_size) {
    const float* inputs = (const float*)d_in[0];
    const float* k_ant  = (const float*)d_in[1];
    const float* v_ant  = (const float*)d_in[2];
    const float* w_q    = (const float*)d_in[3];
    const float* w_k    = (const float*)d_in[4];
    const float* cvw    = (const float*)d_in[5];
    const float* cvb    = (const float*)d_in[6];
    const float* cow    = (const float*)d_in[7];
    const float* cob    = (const float*)d_in[8];
    const float* tk     = (const float*)d_in[9];
    const float* tv     = (const float*)d_in[10];
    float* out = (float*)d_out;

    const int CV_SMEM = (8 + 6 * 34 * 128 + 128 * 128) * 4;   // 170016
    const int CO_SMEM = (6 * 34 * 128 + 128 * 64) * 4;        // 137216
    cudaFuncSetAttribute(conv_v_kernel, cudaFuncAttributeMaxDynamicSharedMemorySize, CV_SMEM);
    cudaFuncSetAttribute(conv_o_kernel, cudaFuncAttributeMaxDynamicSharedMemorySize, CO_SMEM);

    pool_kernel<<<(NB * 2048 + 255) / 256, 256>>>(inputs, NB, 0);
    pool_kernel<<<(NB * NS * 2048 + 255) / 256, 256>>>(k_ant, NB * NS, 1);

    gemm_splitk<<<dim3(8, 1, KSLICES), 256>>>(w_q, 0);
    gemm_splitk<<<dim3(8, 8, KSLICES), 256>>>(w_k, 1);
    reduce_parts<<<(NB * TKD + 255) / 256, 256>>>(0);
    reduce_parts<<<(NB * NS * TKD + 255) / 256, 256>>>(1);

    attn_kernel<<<NB, 256>>>(tk);

    conv_v_kernel<<<dim3(NHD, NB), 256, CV_SMEM>>>(v_ant, cvw, cvb, tv);
    conv_o_kernel<<<dim3(NHD, NB), 256, CO_SMEM>>>(cow, cob, out);
}

// round 2
// speedup vs baseline: 1.2597x; 1.2597x over previous
#include <cuda_runtime.h>

#define NB 32
#define NS 8
#define NHD 8
#define QKIN 8192
#define TKD 512
#define DKH 64
#define KSLICES 16
#define KSLEN 512

typedef unsigned long long u64;

// ---- scratch (static __device__ globals; no allocations) ----
__device__ float g_qa[NB * QKIN];                 // pooled inputs   (32, 8192)
__device__ float g_ka[NB * NS * QKIN];            // pooled k_ant    (256, 8192)
__device__ float g_qpart[KSLICES * NB * TKD];     // split-K partials q
__device__ float g_q[NB * TKD];                   // q (32, 512)
__device__ float g_p[NB * NHD * QKIN];            // p vectors (256, 8192)
__device__ float g_wgt[NB * NHD * NS];            // softmax weights (32, 8, 8)
__device__ float g_x[NB * 1024 * 128];            // attention output image (32,32,32,128)

__constant__ int c_ridx[8] = {0, 0, 0, 0, 0, 1, 2, 3}; // rel-emb row index

// ---- f32x2 packed helpers (sm_100+ PTX) ----
__device__ __forceinline__ u64 pack2(float lo, float hi) {
    u64 r; asm("mov.b64 %0, {%1, %2};" : "=l"(r) : "f"(lo), "f"(hi)); return r;
}
__device__ __forceinline__ void ffma2(u64& acc, u64 a, u64 b) {
    asm("fma.rn.f32x2 %0, %1, %2, %0;" : "+l"(acc) : "l"(a), "l"(b));
}
__device__ __forceinline__ float2 unpack2(u64 v) {
    float2 f; asm("mov.b64 {%0, %1}, %2;" : "=f"(f.x), "=f"(f.y) : "l"(v)); return f;
}

// ---------------- avg pool 4x4 -> flattened (img, 8*8*128) ----------------
__global__ void pool_kernel(const float* __restrict__ in, int nImg, int which) {
    float* out = which ? g_ka : g_qa;
    int idx = blockIdx.x * 256 + threadIdx.x;      // float4 units
    if (idx >= nImg * 2048) return;
    int c4 = idx & 31;
    int pw = (idx >> 5) & 7;
    int ph = (idx >> 8) & 7;
    int img = idx >> 11;
    const float4* p4 = (const float4*)in;
    float sx = 0.f, sy = 0.f, sz = 0.f, sw = 0.f;
#pragma unroll
    for (int i = 0; i < 4; i++)
#pragma unroll
        for (int j = 0; j < 4; j++) {
            float4 v = p4[((img * 32 + ph * 4 + i) * 32 + pw * 4 + j) * 32 + c4];
            sx += v.x; sy += v.y; sz += v.z; sw += v.w;
        }
    ((float4*)out)[idx] = make_float4(sx * 0.0625f, sy * 0.0625f, sz * 0.0625f, sw * 0.0625f);
}

// ---------------- split-K GEMM (q only): C[32,512] = qa[32,8192] @ W[8192,512] ----------------
__global__ __launch_bounds__(256) void gemm_splitk_q(const float* __restrict__ Wm) {
    const float* A = g_qa;
    __shared__ float As[32][33];
    __shared__ float Bs[32][65];
    int nt = blockIdx.x, ks = blockIdx.z;
    int t = threadIdx.x;
    int tx = t & 15, ty = t >> 4;
    float acc[2][4] = {};
    int n0 = nt * 64, kbase = ks * KSLEN;
    for (int kk = 0; kk < KSLEN; kk += 32) {
        int k0 = kbase + kk;
#pragma unroll
        for (int i = 0; i < 4; i++) {
            int e = t + i * 256; int r = e >> 5, c = e & 31;
            As[r][c] = A[r * QKIN + k0 + c];
        }
#pragma unroll
        for (int i = 0; i < 8; i++) {
            int e = t + i * 256; int r = e >> 6, c = e & 63;
            Bs[r][c] = Wm[(k0 + r) * TKD + n0 + c];
        }
        __syncthreads();
#pragma unroll
        for (int k = 0; k < 32; k++) {
            float a0 = As[ty * 2][k], a1 = As[ty * 2 + 1][k];
            float b0 = Bs[k][tx * 4 + 0], b1 = Bs[k][tx * 4 + 1];
            float b2 = Bs[k][tx * 4 + 2], b3 = Bs[k][tx * 4 + 3];
            acc[0][0] = fmaf(a0, b0, acc[0][0]); acc[0][1] = fmaf(a0, b1, acc[0][1]);
            acc[0][2] = fmaf(a0, b2, acc[0][2]); acc[0][3] = fmaf(a0, b3, acc[0][3]);
            acc[1][0] = fmaf(a1, b0, acc[1][0]); acc[1][1] = fmaf(a1, b1, acc[1][1]);
            acc[1][2] = fmaf(a1, b2, acc[1][2]); acc[1][3] = fmaf(a1, b3, acc[1][3]);
        }
        __syncthreads();
    }
#pragma unroll
    for (int r = 0; r < 2; r++)
#pragma unroll
        for (int c = 0; c < 4; c++)
            g_qpart[(ks * NB + ty * 2 + r) * TKD + n0 + tx * 4 + c] = acc[r][c];
}

__global__ void reduce_q() {
    int idx = blockIdx.x * 256 + threadIdx.x;
    if (idx >= NB * TKD) return;
    float s = 0.f;
#pragma unroll
    for (int z = 0; z < KSLICES; z++) s += g_qpart[z * NB * TKD + idx];
    g_q[idx] = s;
}

// ---------------- p vectors: p[b,h,j] = sum_d W_k[j, h*64+d] * q[b, h*64+d] ----------------
// grid (h=8, jt=32), 256 threads. Each thread owns one j = jt*256 + t for all 32 b.
__global__ __launch_bounds__(256) void p_kernel(const float* __restrict__ wk) {
    int h = blockIdx.x;
    int j0 = blockIdx.y * 256;
    __shared__ float qs[32 * 64];        // q[b][d] for this head
    __shared__ float ws[256 * 68];       // W rows (padded stride 68)
    int t = threadIdx.x;
    for (int idx = t; idx < 32 * 64; idx += 256) {
        int b = idx >> 6, d = idx & 63;
        qs[idx] = g_q[b * TKD + h * DKH + d];
    }
    for (int idx = t; idx < 256 * 64; idx += 256) {
        int row = idx >> 6, col = idx & 63;
        ws[row * 68 + col] = wk[(j0 + row) * TKD + h * DKH + col];
    }
    __syncthreads();
    float4 wr[16];
#pragma unroll
    for (int d4 = 0; d4 < 16; d4++) wr[d4] = *(const float4*)&ws[t * 68 + d4 * 4];
    int j = j0 + t;
    for (int b = 0; b < 32; b++) {
        float a = 0.f;
#pragma unroll
        for (int d4 = 0; d4 < 16; d4++) {
            float4 q4 = *(const float4*)&qs[b * 64 + d4 * 4];
            a = fmaf(wr[d4].x, q4.x, a);
            a = fmaf(wr[d4].y, q4.y, a);
            a = fmaf(wr[d4].z, q4.z, a);
            a = fmaf(wr[d4].w, q4.w, a);
        }
        g_p[(b * NHD + h) * QKIN + j] = a;
    }
}

// ---------------- logits = ka . p  (+ q.z_k), softmax -> weights ----------------
// grid (b=32, h=8), 256 threads.
__global__ __launch_bounds__(256) void logits_kernel(const float* __restrict__ tk) {
    int b = blockIdx.x, h = blockIdx.y;
    int t = threadIdx.x;
    const float* pp = g_p + (b * NHD + h) * QKIN;
    const float* ka = g_ka + b * NS * QKIN;
    float acc[8] = {};
    for (int j = t; j < QKIN; j += 256) {
        float pv = pp[j];
#pragma unroll
        for (int s = 0; s < 8; s++) acc[s] = fmaf(ka[s * QKIN + j], pv, acc[s]);
    }
#pragma unroll
    for (int s = 0; s < 8; s++)
#pragma unroll
        for (int off = 16; off; off >>= 1) acc[s] += __shfl_xor_sync(0xffffffffu, acc[s], off);
    __shared__ float red[8][8];
    __shared__ float rel[8];
    int w = t >> 5, lane = t & 31;
    if (lane == 0) {
#pragma unroll
        for (int s = 0; s < 8; s++) red[s][w] = acc[s];
    }
    if (w == 0) {   // rel-emb term: q . z_k
        float qa = g_q[b * TKD + h * DKH + lane];
        float qb = g_q[b * TKD + h * DKH + 32 + lane];
#pragma unroll
        for (int s = 0; s < 8; s++) {
            int r = c_ridx[s];
            float v = qa * tk[r * DKH + lane] + qb * tk[r * DKH + 32 + lane];
#pragma unroll
            for (int off = 16; off; off >>= 1) v += __shfl_xor_sync(0xffffffffu, v, off);
            if (lane == 0) rel[s] = v;
        }
    }
    __syncthreads();
    if (t == 0) {
        float lg[8];
#pragma unroll
        for (int s = 0; s < 8; s++) {
            float d = 0.f;
#pragma unroll
            for (int ww = 0; ww < 8; ww++) d += red[s][ww];
            lg[s] = (d + rel[s]) * 0.125f;     // 1/sqrt(64)
        }
        float m = lg[0];
#pragma unroll
        for (int s = 1; s < 8; s++) m = fmaxf(m, lg[s]);
        float sum = 0.f;
#pragma unroll
        for (int s = 0; s < 8; s++) { lg[s] = expf(lg[s] - m); sum += lg[s]; }
        float inv = 1.f / sum;
#pragma unroll
        for (int s = 0; s < 8; s++) g_wgt[b * 64 + h * 8 + s] = lg[s] * inv;
    }
}

// ---------------- fused: weighted-sum over S + conv_v 3x3 + z_v + bias (f32x2) ----------------
__global__ __launch_bounds__(256, 1) void conv_v_kernel(
    const float* __restrict__ v_ant, const float* __restrict__ cw,
    const float* __restrict__ cb, const float* __restrict__ tv) {
    int h = blockIdx.x, b = blockIdx.y;
    extern __shared__ float sm[];
    float* s_wgt = sm;
    float* s_in  = sm + 8;
    float* s_w   = sm + 8 + 6 * 34 * 128;
    int t = threadIdx.x;
    if (t < 8) s_wgt[t] = g_wgt[b * 64 + h * 8 + t];
    __syncthreads();

    // weighted input tile: rows 4h-1..4h+4, cols -1..32, zero padded
    for (int e = t; e < 6 * 34 * 32; e += 256) {
        int c4 = e & 31;
        int ci = (e >> 5) % 34;
        int ri = e / (34 * 32);
        int gr = h * 4 - 1 + ri;
        int gc = ci - 1;
        float ax = 0.f, ay = 0.f, az = 0.f, aw = 0.f;
        if (gr >= 0 && gr < 32 && gc >= 0 && gc < 32) {
            const float4* vp = (const float4*)v_ant;
            int base = (b * 8 * 1024 + gr * 32 + gc) * 32 + c4;
#pragma unroll
            for (int s = 0; s < 8; s++) {
                float4 vv = vp[base + s * 32768];
                float w = s_wgt[s];
                ax = fmaf(w, vv.x, ax); ay = fmaf(w, vv.y, ay);
                az = fmaf(w, vv.z, az); aw = fmaf(w, vv.w, aw);
            }
        }
        *(float4*)&s_in[(ri * 34 + ci) * 128 + c4 * 4] = make_float4(ax, ay, az, aw);
    }

    int tx = t & 15, ty = t >> 4;
    u64 acc[8][4];
#pragma unroll
    for (int i = 0; i < 8; i++)
#pragma unroll
        for (int p = 0; p < 4; p++) acc[i][p] = 0ull;
    int sbase[8];
#pragma unroll
    for (int i = 0; i < 8; i++) {
        int p = ty + i * 16;
        sbase[i] = (((p >> 5) + 1) * 34 + (p & 31) + 1) * 128;
    }

    for (int tap = 0; tap < 9; tap++) {
        __syncthreads();
        for (int e = t; e < 4096; e += 256)
            *(float4*)&s_w[e * 4] = *(const float4*)&cw[tap * 16384 + e * 4];
        __syncthreads();
        int dy = tap / 3 - 1, dx = tap % 3 - 1;
        int doff = (dy * 34 + dx) * 128;
#pragma unroll 2
        for (int cin = 0; cin < 128; cin++) {
            float4 bA = *(const float4*)&s_w[cin * 128 + tx * 8];
            float4 bB = *(const float4*)&s_w[cin * 128 + tx * 8 + 4];
            u64 b0 = pack2(bA.x, bA.y), b1 = pack2(bA.z, bA.w);
            u64 b2 = pack2(bB.x, bB.y), b3 = pack2(bB.z, bB.w);
#pragma unroll
            for (int i = 0; i < 8; i++) {
                float a = s_in[sbase[i] + doff + cin];
                u64 aa = pack2(a, a);
                ffma2(acc[i][0], aa, b0);
                ffma2(acc[i][1], aa, b1);
                ffma2(acc[i][2], aa, b2);
                ffma2(acc[i][3], aa, b3);
            }
        }
    }

    // epilogue: + bias + weighted z_v, store image layout
    const float4* cb4 = (const float4*)cb;
    float4 bias0 = cb4[tx * 2], bias1 = cb4[tx * 2 + 1];
#pragma unroll
    for (int i = 0; i < 8; i++) {
        int p = ty + i * 16;
        float r0x = bias0.x, r0y = bias0.y, r0z = bias0.z, r0w = bias0.w;
        float r1x = bias1.x, r1y = bias1.y, r1z = bias1.z, r1w = bias1.w;
#pragma unroll
        for (int s = 0; s < 8; s++) {
            float w = s_wgt[s];
            const float4* tp = (const float4*)&tv[c_ridx[s] * 16384 + p * 128 + tx * 8];
            float4 t0 = tp[0], t1 = tp[1];
            r0x = fmaf(w, t0.x, r0x); r0y = fmaf(w, t0.y, r0y);
            r0z = fmaf(w, t0.z, r0z); r0w = fmaf(w, t0.w, r0w);
            r1x = fmaf(w, t1.x, r1x); r1y = fmaf(w, t1.y, r1y);
            r1z = fmaf(w, t1.z, r1z); r1w = fmaf(w, t1.w, r1w);
        }
        float2 a0 = unpack2(acc[i][0]), a1 = unpack2(acc[i][1]);
        float2 a2 = unpack2(acc[i][2]), a3 = unpack2(acc[i][3]);
        int gr = h * 4 + (p >> 5), gc = p & 31;
        float4* xp = (float4*)&g_x[(b * 1024 + gr * 32 + gc) * 128 + tx * 8];
        xp[0] = make_float4(a0.x + r0x, a0.y + r0y, a1.x + r0z, a1.y + r0w);
        xp[1] = make_float4(a2.x + r1x, a2.y + r1y, a3.x + r1z, a3.y + r1w);
    }
}

// ---------------- conv_o 3x3: (32,32,32,128) -> (32,32,32,64) (f32x2) ----------------
__global__ __launch_bounds__(256, 1) void conv_o_kernel(
    const float* __restrict__ cw, const float* __restrict__ cb, float* __restrict__ out) {
    int rb = blockIdx.x, b = blockIdx.y;
    extern __shared__ float sm[];
    float* s_in = sm;                 // 6*34*128
    float* s_w  = sm + 6 * 34 * 128;  // 128*64
    int t = threadIdx.x;
    for (int e = t; e < 6 * 34 * 32; e += 256) {
        int c4 = e & 31;
        int ci = (e >> 5) % 34;
        int ri = e / (34 * 32);
        int gr = rb * 4 - 1 + ri, gc = ci - 1;
        float4 v = make_float4(0, 0, 0, 0);
        if (gr >= 0 && gr < 32 && gc >= 0 && gc < 32)
            v = *(const float4*)&g_x[(b * 1024 + gr * 32 + gc) * 128 + c4 * 4];
        *(float4*)&s_in[(ri * 34 + ci) * 128 + c4 * 4] = v;
    }
    int tx = t & 7, ty = t >> 3;
    u64 acc[4][4];
#pragma unroll
    for (int i = 0; i < 4; i++)
#pragma unroll
        for (int p = 0; p < 4; p++) acc[i][p] = 0ull;
    int sbase[4];
#pragma unroll
    for (int i = 0; i < 4; i++) {
        int p = ty + i * 32;
        sbase[i] = (((p >> 5) + 1) * 34 + (p & 31) + 1) * 128;
    }
    for (int tap = 0; tap < 9; tap++) {
        __syncthreads();
        for (int e = t; e < 2048; e += 256)
            *(float4*)&s_w[e * 4] = *(const float4*)&cw[tap * 8192 + e * 4];
        __syncthreads();
        int dy = tap / 3 - 1, dx = tap % 3 - 1;
        int doff = (dy * 34 + dx) * 128;
#pragma unroll 2
        for (int cin = 0; cin < 128; cin++) {
            float4 bA = *(const float4*)&s_w[cin * 64 + tx * 8];
            float4 bB = *(const float4*)&s_w[cin * 64 + tx * 8 + 4];
            u64 b0 = pack2(bA.x, bA.y), b1 = pack2(bA.z, bA.w);
            u64 b2 = pack2(bB.x, bB.y), b3 = pack2(bB.z, bB.w);
#pragma unroll
            for (int i = 0; i < 4; i++) {
                float a = s_in[sbase[i] + doff + cin];
                u64 aa = pack2(a, a);
                ffma2(acc[i][0], aa, b0);
                ffma2(acc[i][1], aa, b1);
                ffma2(acc[i][2], aa, b2);
                ffma2(acc[i][3], aa, b3);
            }
        }
    }
    const float4* cb4 = (const float4*)cb;
    float4 bias0 = cb4[tx * 2], bias1 = cb4[tx * 2 + 1];
#pragma unroll
    for (int i = 0; i < 4; i++) {
        int p = ty + i * 32;
        int gr = rb * 4 + (p >> 5), gc = p & 31;
        float2 a0 = unpack2(acc[i][0]), a1 = unpack2(acc[i][1]);
        float2 a2 = unpack2(acc[i][2]), a3 = unpack2(acc[i][3]);
        float4* op = (float4*)&out[(b * 1024 + gr * 32 + gc) * 64 + tx * 8];
        op[0] = make_float4(a0.x + bias0.x, a0.y + bias0.y, a1.x + bias0.z, a1.y + bias0.w);
        op[1] = make_float4(a2.x + bias1.x, a2.y + bias1.y, a3.x + bias1.z, a3.y + bias1.w);
    }
}

extern "C" void kernel_launch(void* const* d_in, const int* in_sizes, int n_in,
                              void* d_out, int out_size) {
    const float* inputs = (const float*)d_in[0];
    const float* k_ant  = (const float*)d_in[1];
    const float* v_ant  = (const float*)d_in[2];
    const float* w_q    = (const float*)d_in[3];
    const float* w_k    = (const float*)d_in[4];
    const float* cvw    = (const float*)d_in[5];
    const float* cvb    = (const float*)d_in[6];
    const float* cow    = (const float*)d_in[7];
    const float* cob    = (const float*)d_in[8];
    const float* tk     = (const float*)d_in[9];
    const float* tv     = (const float*)d_in[10];
    float* out = (float*)d_out;

    const int CV_SMEM = (8 + 6 * 34 * 128 + 128 * 128) * 4;   // 170016
    const int CO_SMEM = (6 * 34 * 128 + 128 * 64) * 4;        // 137216
    cudaFuncSetAttribute(conv_v_kernel, cudaFuncAttributeMaxDynamicSharedMemorySize, CV_SMEM);
    cudaFuncSetAttribute(conv_o_kernel, cudaFuncAttributeMaxDynamicSharedMemorySize, CO_SMEM);

    pool_kernel<<<(NB * 2048 + 255) / 256, 256>>>(inputs, NB, 0);
    pool_kernel<<<(NB * NS * 2048 + 255) / 256, 256>>>(k_ant, NB * NS, 1);

    gemm_splitk_q<<<dim3(8, 1, KSLICES), 256>>>(w_q);
    reduce_q<<<(NB * TKD + 255) / 256, 256>>>();

    p_kernel<<<dim3(NHD, 32), 256>>>(w_k);
    logits_kernel<<<dim3(NB, NHD), 256>>>(tk);

    conv_v_kernel<<<dim3(NHD, NB), 256, CV_SMEM>>>(v_ant, cvw, cvb, tv);
    conv_o_kernel<<<dim3(NHD, NB), 256, CO_SMEM>>>(cow, cob, out);
}

// round 4
// speedup vs baseline: 3.0347x; 2.4092x over previous
#include <cuda_runtime.h>
#include <cstdint>

#define NB 32
#define NS 8
#define NHD 8
#define QKIN 8192
#define TKD 512
#define DKH 64
#define KSLICES 16
#define KSLEN 512

typedef unsigned long long u64;
typedef unsigned int u32;

// ---- scratch (static __device__ globals; no allocations) ----
__device__ float g_qa[NB * QKIN];
__device__ float g_ka[NB * NS * QKIN];
__device__ float g_qpart[KSLICES * NB * TKD];
__device__ float g_q[NB * TKD];
__device__ float g_p[NB * NHD * QKIN];
__device__ float g_wgt[NB * NHD * NS];
__device__ float g_x[NB * 1024 * 128];
// mma-fragment-packed weights: [tap][ntile][kstep][lane] float2 (b0,b1), tf32-rounded
__device__ float2 g_wBv[9 * 16 * 16 * 32];   // conv_v: 16 ntiles (128 out)
__device__ float2 g_wBo[9 * 8 * 16 * 32];    // conv_o: 8 ntiles (64 out)

__constant__ int c_ridx[8] = {0, 0, 0, 0, 0, 1, 2, 3};

__device__ __forceinline__ float tf32r(float x) {
    float y; asm("cvt.rna.tf32.f32 %0, %1;" : "=f"(y) : "f"(x)); return y;
}

__device__ __forceinline__ void mma_tf32(float4& d, const u32* a, float2 b) {
    asm volatile("mma.sync.aligned.m16n8k8.row.col.f32.tf32.tf32.f32 "
        "{%0,%1,%2,%3}, {%4,%5,%6,%7}, {%8,%9}, {%0,%1,%2,%3};"
        : "+f"(d.x), "+f"(d.y), "+f"(d.z), "+f"(d.w)
        : "r"(a[0]), "r"(a[1]), "r"(a[2]), "r"(a[3]),
          "r"(__float_as_uint(b.x)), "r"(__float_as_uint(b.y)));
}

// ======================= pool =======================
__global__ void pool_kernel(const float* __restrict__ in, int nImg, int which) {
    float* out = which ? g_ka : g_qa;
    int idx = blockIdx.x * 256 + threadIdx.x;
    if (idx >= nImg * 2048) return;
    int c4 = idx & 31;
    int pw = (idx >> 5) & 7;
    int ph = (idx >> 8) & 7;
    int img = idx >> 11;
    const float4* p4 = (const float4*)in;
    float sx = 0.f, sy = 0.f, sz = 0.f, sw = 0.f;
#pragma unroll
    for (int i = 0; i < 4; i++)
#pragma unroll
        for (int j = 0; j < 4; j++) {
            float4 v = p4[((img * 32 + ph * 4 + i) * 32 + pw * 4 + j) * 32 + c4];
            sx += v.x; sy += v.y; sz += v.z; sw += v.w;
        }
    ((float4*)out)[idx] = make_float4(sx * 0.0625f, sy * 0.0625f, sz * 0.0625f, sw * 0.0625f);
}

// ======================= q GEMM (split-K) =======================
__global__ __launch_bounds__(256) void gemm_splitk_q(const float* __restrict__ Wm) {
    const float* A = g_qa;
    __shared__ float As[32][33];
    __shared__ float Bs[32][65];
    int nt = blockIdx.x, ks = blockIdx.z;
    int t = threadIdx.x;
    int tx = t & 15, ty = t >> 4;
    float acc[2][4] = {};
    int n0 = nt * 64, kbase = ks * KSLEN;
    for (int kk = 0; kk < KSLEN; kk += 32) {
        int k0 = kbase + kk;
#pragma unroll
        for (int i = 0; i < 4; i++) {
            int e = t + i * 256; int r = e >> 5, c = e & 31;
            As[r][c] = A[r * QKIN + k0 + c];
        }
#pragma unroll
        for (int i = 0; i < 8; i++) {
            int e = t + i * 256; int r = e >> 6, c = e & 63;
            Bs[r][c] = Wm[(k0 + r) * TKD + n0 + c];
        }
        __syncthreads();
#pragma unroll
        for (int k = 0; k < 32; k++) {
            float a0 = As[ty * 2][k], a1 = As[ty * 2 + 1][k];
            float b0 = Bs[k][tx * 4 + 0], b1 = Bs[k][tx * 4 + 1];
            float b2 = Bs[k][tx * 4 + 2], b3 = Bs[k][tx * 4 + 3];
            acc[0][0] = fmaf(a0, b0, acc[0][0]); acc[0][1] = fmaf(a0, b1, acc[0][1]);
            acc[0][2] = fmaf(a0, b2, acc[0][2]); acc[0][3] = fmaf(a0, b3, acc[0][3]);
            acc[1][0] = fmaf(a1, b0, acc[1][0]); acc[1][1] = fmaf(a1, b1, acc[1][1]);
            acc[1][2] = fmaf(a1, b2, acc[1][2]); acc[1][3] = fmaf(a1, b3, acc[1][3]);
        }
        __syncthreads();
    }
#pragma unroll
    for (int r = 0; r < 2; r++)
#pragma unroll
        for (int c = 0; c < 4; c++)
            g_qpart[(ks * NB + ty * 2 + r) * TKD + n0 + tx * 4 + c] = acc[r][c];
}

__global__ void reduce_q() {
    int idx = blockIdx.x * 256 + threadIdx.x;
    if (idx >= NB * TKD) return;
    float s = 0.f;
#pragma unroll
    for (int z = 0; z < KSLICES; z++) s += g_qpart[z * NB * TKD + idx];
    g_q[idx] = s;
}

// ======================= p vectors =======================
__global__ __launch_bounds__(256) void p_kernel(const float* __restrict__ wk) {
    int h = blockIdx.x;
    int j0 = blockIdx.y * 256;
    __shared__ float qs[32 * 64];
    __shared__ float ws[256 * 68];
    int t = threadIdx.x;
    for (int idx = t; idx < 32 * 64; idx += 256) {
        int b = idx >> 6, d = idx & 63;
        qs[idx] = g_q[b * TKD + h * DKH + d];
    }
    for (int idx = t; idx < 256 * 64; idx += 256) {
        int row = idx >> 6, col = idx & 63;
        ws[row * 68 + col] = wk[(j0 + row) * TKD + h * DKH + col];
    }
    __syncthreads();
    float4 wr[16];
#pragma unroll
    for (int d4 = 0; d4 < 16; d4++) wr[d4] = *(const float4*)&ws[t * 68 + d4 * 4];
    int j = j0 + t;
    for (int b = 0; b < 32; b++) {
        float a = 0.f;
#pragma unroll
        for (int d4 = 0; d4 < 16; d4++) {
            float4 q4 = *(const float4*)&qs[b * 64 + d4 * 4];
            a = fmaf(wr[d4].x, q4.x, a);
            a = fmaf(wr[d4].y, q4.y, a);
            a = fmaf(wr[d4].z, q4.z, a);
            a = fmaf(wr[d4].w, q4.w, a);
        }
        g_p[(b * NHD + h) * QKIN + j] = a;
    }
}

// ======================= logits + softmax =======================
__global__ __launch_bounds__(256) void logits_kernel(const float* __restrict__ tk) {
    int b = blockIdx.x, h = blockIdx.y;
    int t = threadIdx.x;
    const float* pp = g_p + (b * NHD + h) * QKIN;
    const float* ka = g_ka + b * NS * QKIN;
    float acc[8] = {};
    for (int j = t; j < QKIN; j += 256) {
        float pv = pp[j];
#pragma unroll
        for (int s = 0; s < 8; s++) acc[s] = fmaf(ka[s * QKIN + j], pv, acc[s]);
    }
#pragma unroll
    for (int s = 0; s < 8; s++)
#pragma unroll
        for (int off = 16; off; off >>= 1) acc[s] += __shfl_xor_sync(0xffffffffu, acc[s], off);
    __shared__ float red[8][8];
    __shared__ float rel[8];
    int w = t >> 5, lane = t & 31;
    if (lane == 0) {
#pragma unroll
        for (int s = 0; s < 8; s++) red[s][w] = acc[s];
    }
    if (w == 0) {
        float qa = g_q[b * TKD + h * DKH + lane];
        float qb = g_q[b * TKD + h * DKH + 32 + lane];
#pragma unroll
        for (int s = 0; s < 8; s++) {
            int r = c_ridx[s];
            float v = qa * tk[r * DKH + lane] + qb * tk[r * DKH + 32 + lane];
#pragma unroll
            for (int off = 16; off; off >>= 1) v += __shfl_xor_sync(0xffffffffu, v, off);
            if (lane == 0) rel[s] = v;
        }
    }
    __syncthreads();
    if (t == 0) {
        float lg[8];
#pragma unroll
        for (int s = 0; s < 8; s++) {
            float d = 0.f;
#pragma unroll
            for (int ww = 0; ww < 8; ww++) d += red[s][ww];
            lg[s] = (d + rel[s]) * 0.125f;
        }
        float m = lg[0];
#pragma unroll
        for (int s = 1; s < 8; s++) m = fmaxf(m, lg[s]);
        float sum = 0.f;
#pragma unroll
        for (int s = 0; s < 8; s++) { lg[s] = expf(lg[s] - m); sum += lg[s]; }
        float inv = 1.f / sum;
#pragma unroll
        for (int s = 0; s < 8; s++) g_wgt[b * 64 + h * 8 + s] = lg[s] * inv;
    }
}

// ======================= weight fragment packer =======================
// B frag for mma.m16n8k8.row.col: b0 = B[lane%4][lane/4], b1 = B[lane%4+4][lane/4]
// where B[k][n] = W[cin0+k][o0+n]. cvw layout: ((tap)*128 + cin)*128 + o (HWIO).
__global__ void wtrans_kernel(const float* __restrict__ cvw, const float* __restrict__ cow) {
    int t = blockIdx.x * 256 + threadIdx.x;
    if (t < 9 * 16 * 16 * 32) {
        int lane = t & 31, k = (t >> 5) & 15, nt = (t >> 9) & 15, tap = t >> 13;
        int o = nt * 8 + (lane >> 2);
        int cin = k * 8 + (lane & 3);
        float b0 = cvw[(tap * 128 + cin) * 128 + o];
        float b1 = cvw[(tap * 128 + cin + 4) * 128 + o];
        g_wBv[t] = make_float2(tf32r(b0), tf32r(b1));
    } else {
        int e = t - 9 * 16 * 16 * 32;
        if (e < 9 * 8 * 16 * 32) {
            int lane = e & 31, k = (e >> 5) & 15, nt = (e >> 9) & 7, tap = e >> 12;
            int o = nt * 8 + (lane >> 2);
            int cin = k * 8 + (lane & 3);
            float b0 = cow[(tap * 128 + cin) * 64 + o];
            float b1 = cow[(tap * 128 + cin + 4) * 64 + o];
            g_wBo[e] = make_float2(tf32r(b0), tf32r(b1));
        }
    }
}

// smem: s_w 16384 | s_wgt 8 | s_in 204*132
#define CV_SMEM_BYTES ((16392 + 204 * 132) * 4)

// ======================= conv_v: weighted-sum + 3x3 conv via mma tf32 =======================
__global__ __launch_bounds__(256, 1) void conv_v_kernel(
    const float* __restrict__ v_ant, const float* __restrict__ cvb,
    const float* __restrict__ tv) {
    int h = blockIdx.x, b = blockIdx.y;
    extern __shared__ float sm[];
    float* s_w   = sm;            // 16384 floats (one tap of frag-packed B)
    float* s_wgt = sm + 16384;    // 8
    float* s_in  = sm + 16392;    // 204*132
    int t = threadIdx.x;
    int wid = t >> 5, lane = t & 31;
    if (t < 8) s_wgt[t] = g_wgt[b * 64 + h * 8 + t];
    __syncthreads();

    // weighted input tile: rows 4h-1..4h+4, cols -1..32, tf32-rounded, stride 132
    for (int e = t; e < 6 * 34 * 32; e += 256) {
        int c4 = e & 31;
        int ci = (e >> 5) % 34;
        int ri = e / (34 * 32);
        int gr = h * 4 - 1 + ri;
        int gc = ci - 1;
        float ax = 0.f, ay = 0.f, az = 0.f, aw = 0.f;
        if (gr >= 0 && gr < 32 && gc >= 0 && gc < 32) {
            const float4* vp = (const float4*)v_ant;
            int base = (b * 8 * 1024 + gr * 32 + gc) * 32 + c4;
#pragma unroll
            for (int s = 0; s < 8; s++) {
                float4 vv = vp[base + s * 32768];
                float w = s_wgt[s];
                ax = fmaf(w, vv.x, ax); ay = fmaf(w, vv.y, ay);
                az = fmaf(w, vv.z, az); aw = fmaf(w, vv.w, aw);
            }
        }
        *(float4*)&s_in[(ri * 34 + ci) * 132 + c4 * 4] =
            make_float4(tf32r(ax), tf32r(ay), tf32r(az), tf32r(aw));
    }

    int mw = wid >> 1, nw = wid & 1;   // 4 pixel-row groups x 2 out-halves
    float4 acc[2][8];
#pragma unroll
    for (int m = 0; m < 2; m++)
#pragma unroll
        for (int nt = 0; nt < 8; nt++) acc[m][nt] = make_float4(0.f, 0.f, 0.f, 0.f);

    for (int tap = 0; tap < 9; tap++) {
        __syncthreads();
        const float4* srcw = (const float4*)(g_wBv + tap * 8192);
        float4* dw = (float4*)s_w;
        for (int e = t; e < 4096; e += 256) dw[e] = srcw[e];
        __syncthreads();
        int dy = tap / 3 - 1, dx = tap % 3 - 1;
        const float* ab = s_in + ((mw + 1 + dy) * 34 + 1 + dx) * 132;
        const float2* s_w2 = (const float2*)s_w;
#pragma unroll
        for (int k = 0; k < 16; k++) {
            int cin = k * 8 + (lane & 3);
            u32 a[2][4];
#pragma unroll
            for (int m = 0; m < 2; m++) {
                int c = m * 16 + (lane >> 2);
                a[m][0] = __float_as_uint(ab[c * 132 + cin]);
                a[m][1] = __float_as_uint(ab[(c + 8) * 132 + cin]);
                a[m][2] = __float_as_uint(ab[c * 132 + cin + 4]);
                a[m][3] = __float_as_uint(ab[(c + 8) * 132 + cin + 4]);
            }
#pragma unroll
            for (int nt = 0; nt < 8; nt++) {
                float2 bv = s_w2[((nw * 8 + nt) * 16 + k) * 32 + lane];
                mma_tf32(acc[0][nt], a[0], bv);
                mma_tf32(acc[1][nt], a[1], bv);
            }
        }
    }

    // epilogue: + bias + weighted z_v -> g_x
    float W0 = s_wgt[0] + s_wgt[1] + s_wgt[2] + s_wgt[3] + s_wgt[4];
    float w5 = s_wgt[5], w6 = s_wgt[6], w7 = s_wgt[7];
    const float2* tv2 = (const float2*)tv;
#pragma unroll
    for (int m = 0; m < 2; m++) {
#pragma unroll
        for (int half = 0; half < 2; half++) {
            int p = mw * 32 + m * 16 + (lane >> 2) + half * 8;  // local pixel in head tile
            int gr = h * 4 + (p >> 5), gc = p & 31;
            float* dst = &g_x[(b * 1024 + gr * 32 + gc) * 128];
#pragma unroll
            for (int nt = 0; nt < 8; nt++) {
                int o = nw * 64 + nt * 8 + (lane & 3) * 2;
                int ti = p * 64 + (o >> 1);
                float2 z0 = tv2[ti];
                float2 z1 = tv2[8192 + ti];
                float2 z2 = tv2[16384 + ti];
                float2 z3 = tv2[24576 + ti];
                float2 bias = *(const float2*)&cvb[o];
                float ax = half ? acc[m][nt].z : acc[m][nt].x;
                float ay = half ? acc[m][nt].w : acc[m][nt].y;
                float2 r;
                r.x = ax + bias.x + W0 * z0.x + w5 * z1.x + w6 * z2.x + w7 * z3.x;
                r.y = ay + bias.y + W0 * z0.y + w5 * z1.y + w6 * z2.y + w7 * z3.y;
                *(float2*)&dst[o] = r;
            }
        }
    }
}

// smem: s_w 8192 | s_in 204*132
#define CO_SMEM_BYTES ((8192 + 204 * 132) * 4)

// ======================= conv_o: 3x3 conv 128->64 via mma tf32 =======================
__global__ __launch_bounds__(256, 1) void conv_o_kernel(
    const float* __restrict__ cob, float* __restrict__ out) {
    int rb = blockIdx.x, b = blockIdx.y;
    extern __shared__ float sm[];
    float* s_w  = sm;          // 8192
    float* s_in = sm + 8192;   // 204*132
    int t = threadIdx.x;
    int wid = t >> 5, lane = t & 31;

    for (int e = t; e < 6 * 34 * 32; e += 256) {
        int c4 = e & 31;
        int ci = (e >> 5) % 34;
        int ri = e / (34 * 32);
        int gr = rb * 4 - 1 + ri, gc = ci - 1;
        float4 v = make_float4(0.f, 0.f, 0.f, 0.f);
        if (gr >= 0 && gr < 32 && gc >= 0 && gc < 32) {
            v = *(const float4*)&g_x[(b * 1024 + gr * 32 + gc) * 128 + c4 * 4];
            v = make_float4(tf32r(v.x), tf32r(v.y), tf32r(v.z), tf32r(v.w));
        }
        *(float4*)&s_in[(ri * 34 + ci) * 132 + c4 * 4] = v;
    }

    int mw = wid >> 1, nw = wid & 1;
    float4 acc[2][4];
#pragma unroll
    for (int m = 0; m < 2; m++)
#pragma unroll
        for (int nt = 0; nt < 4; nt++) acc[m][nt] = make_float4(0.f, 0.f, 0.f, 0.f);

    for (int tap = 0; tap < 9; tap++) {
        __syncthreads();
        const float4* srcw = (const float4*)(g_wBo + tap * 4096);
        float4* dw = (float4*)s_w;
        for (int e = t; e < 2048; e += 256) dw[e] = srcw[e];
        __syncthreads();
        int dy = tap / 3 - 1, dx = tap % 3 - 1;
        const float* ab = s_in + ((mw + 1 + dy) * 34 + 1 + dx) * 132;
        const float2* s_w2 = (const float2*)s_w;
#pragma unroll
        for (int k = 0; k < 16; k++) {
            int cin = k * 8 + (lane & 3);
            u32 a[2][4];
#pragma unroll
            for (int m = 0; m < 2; m++) {
                int c = m * 16 + (lane >> 2);
                a[m][0] = __float_as_uint(ab[c * 132 + cin]);
                a[m][1] = __float_as_uint(ab[(c + 8) * 132 + cin]);
                a[m][2] = __float_as_uint(ab[c * 132 + cin + 4]);
                a[m][3] = __float_as_uint(ab[(c + 8) * 132 + cin + 4]);
            }
#pragma unroll
            for (int nt = 0; nt < 4; nt++) {
                float2 bv = s_w2[((nw * 4 + nt) * 16 + k) * 32 + lane];
                mma_tf32(acc[0][nt], a[0], bv);
                mma_tf32(acc[1][nt], a[1], bv);
            }
        }
    }

#pragma unroll
    for (int m = 0; m < 2; m++) {
#pragma unroll
        for (int half = 0; half < 2; half++) {
            int p = mw * 32 + m * 16 + (lane >> 2) + half * 8;
            int gr = rb * 4 + (p >> 5), gc = p & 31;
            float* dst = &out[(b * 1024 + gr * 32 + gc) * 64];
#pragma unroll
            for (int nt = 0; nt < 4; nt++) {
                int o = nw * 32 + nt * 8 + (lane & 3) * 2;
                float2 bias = *(const float2*)&cob[o];
                float ax = half ? acc[m][nt].z : acc[m][nt].x;
                float ay = half ? acc[m][nt].w : acc[m][nt].y;
                float2 r;
                r.x = ax + bias.x;
                r.y = ay + bias.y;
                *(float2*)&dst[o] = r;
            }
        }
    }
}

extern "C" void kernel_launch(void* const* d_in, const int* in_sizes, int n_in,
                              void* d_out, int out_size) {
    const float* inputs = (const float*)d_in[0];
    const float* k_ant  = (const float*)d_in[1];
    const float* v_ant  = (const float*)d_in[2];
    const float* w_q    = (const float*)d_in[3];
    const float* w_k    = (const float*)d_in[4];
    const float* cvw    = (const float*)d_in[5];
    const float* cvb    = (const float*)d_in[6];
    const float* cow    = (const float*)d_in[7];
    const float* cob    = (const float*)d_in[8];
    const float* tk     = (const float*)d_in[9];
    const float* tv     = (const float*)d_in[10];
    float* out = (float*)d_out;

    cudaFuncSetAttribute(conv_v_kernel, cudaFuncAttributeMaxDynamicSharedMemorySize, CV_SMEM_BYTES);
    cudaFuncSetAttribute(conv_o_kernel, cudaFuncAttributeMaxDynamicSharedMemorySize, CO_SMEM_BYTES);

    wtrans_kernel<<<(9 * 16 * 16 * 32 + 9 * 8 * 16 * 32 + 255) / 256, 256>>>(cvw, cow);

    pool_kernel<<<(NB * 2048 + 255) / 256, 256>>>(inputs, NB, 0);
    pool_kernel<<<(NB * NS * 2048 + 255) / 256, 256>>>(k_ant, NB * NS, 1);

    gemm_splitk_q<<<dim3(8, 1, KSLICES), 256>>>(w_q);
    reduce_q<<<(NB * TKD + 255) / 256, 256>>>();

    p_kernel<<<dim3(NHD, 32), 256>>>(w_k);
    logits_kernel<<<dim3(NB, NHD), 256>>>(tk);

    conv_v_kernel<<<dim3(NHD, NB), 256, CV_SMEM_BYTES>>>(v_ant, cvb, tv);
    conv_o_kernel<<<dim3(8, NB), 256, CO_SMEM_BYTES>>>(cob, out);
}

// round 5
// speedup vs baseline: 3.1885x; 1.0507x over previous
#include <cuda_runtime.h>
#include <cstdint>

#define NB 32
#define NS 8
#define NHD 8
#define QKIN 8192
#define TKD 512
#define DKH 64
#define KSLICES 32
#define KSLEN 256

typedef unsigned long long u64;
typedef unsigned int u32;

// ---- scratch (static __device__ globals; no allocations) ----
__device__ float g_qa[NB * QKIN];
__device__ float g_ka[NB * NS * QKIN];
__device__ float g_qpart[KSLICES * NB * TKD];
__device__ float g_q[NB * TKD];
__device__ float g_p[NB * NHD * QKIN];
__device__ float g_lgp[NB * 4 * 64];         // logits partials [b][jc][h*8+s]
__device__ float g_wgt[NB * NHD * NS];
__device__ float g_x[NB * 1024 * 128];
__device__ float2 g_wBv[9 * 16 * 16 * 32];
__device__ float2 g_wBo[9 * 8 * 16 * 32];

__constant__ int c_ridx[8] = {0, 0, 0, 0, 0, 1, 2, 3};

__device__ __forceinline__ float tf32r(float x) {
    float y; asm("cvt.rna.tf32.f32 %0, %1;" : "=f"(y) : "f"(x)); return y;
}

__device__ __forceinline__ void mma_tf32(float4& d, const u32* a, float2 b) {
    asm volatile("mma.sync.aligned.m16n8k8.row.col.f32.tf32.tf32.f32 "
        "{%0,%1,%2,%3}, {%4,%5,%6,%7}, {%8,%9}, {%0,%1,%2,%3};"
        : "+f"(d.x), "+f"(d.y), "+f"(d.z), "+f"(d.w)
        : "r"(a[0]), "r"(a[1]), "r"(a[2]), "r"(a[3]),
          "r"(__float_as_uint(b.x)), "r"(__float_as_uint(b.y)));
}

// ======================= pool =======================
__global__ void pool_kernel(const float* __restrict__ in, int nImg, int which) {
    float* out = which ? g_ka : g_qa;
    int idx = blockIdx.x * 256 + threadIdx.x;
    if (idx >= nImg * 2048) return;
    int c4 = idx & 31;
    int pw = (idx >> 5) & 7;
    int ph = (idx >> 8) & 7;
    int img = idx >> 11;
    const float4* p4 = (const float4*)in;
    float sx = 0.f, sy = 0.f, sz = 0.f, sw = 0.f;
#pragma unroll
    for (int i = 0; i < 4; i++)
#pragma unroll
        for (int j = 0; j < 4; j++) {
            float4 v = p4[((img * 32 + ph * 4 + i) * 32 + pw * 4 + j) * 32 + c4];
            sx += v.x; sy += v.y; sz += v.z; sw += v.w;
        }
    ((float4*)out)[idx] = make_float4(sx * 0.0625f, sy * 0.0625f, sz * 0.0625f, sw * 0.0625f);
}

// ======================= q GEMM (split-K, pipelined) =======================
__global__ __launch_bounds__(256, 2) void gemm_splitk_q(const float* __restrict__ Wm) {
    __shared__ float As[32][36];
    __shared__ float Bs[32][68];
    int nt = blockIdx.x, ks = blockIdx.y;
    int t = threadIdx.x;
    int tx = t & 15, ty = t >> 4;
    float acc[2][4] = {};
    int n0 = nt * 64, kbase = ks * KSLEN;
    const float* A = g_qa;
    int ar = t >> 3, ac = (t & 7) * 4;       // A: 32 rows x 8 float4
    int wr = t >> 4, wc = (t & 15) * 4;      // W: rows 0-15 / 16-31, 16 float4 per row
    float4 aP  = *(const float4*)&A[ar * QKIN + kbase + ac];
    float4 wP0 = *(const float4*)&Wm[(kbase + wr) * TKD + n0 + wc];
    float4 wP1 = *(const float4*)&Wm[(kbase + wr + 16) * TKD + n0 + wc];
#pragma unroll
    for (int kt = 0; kt < KSLEN / 32; kt++) {
        __syncthreads();
        *(float4*)&As[ar][ac] = aP;
        *(float4*)&Bs[wr][wc] = wP0;
        *(float4*)&Bs[wr + 16][wc] = wP1;
        __syncthreads();
        if (kt + 1 < KSLEN / 32) {
            int k0 = kbase + (kt + 1) * 32;
            aP  = *(const float4*)&A[ar * QKIN + k0 + ac];
            wP0 = *(const float4*)&Wm[(k0 + wr) * TKD + n0 + wc];
            wP1 = *(const float4*)&Wm[(k0 + wr + 16) * TKD + n0 + wc];
        }
#pragma unroll
        for (int k = 0; k < 32; k++) {
            float a0 = As[ty * 2][k], a1 = As[ty * 2 + 1][k];
            float4 bv = *(const float4*)&Bs[k][tx * 4];
            acc[0][0] = fmaf(a0, bv.x, acc[0][0]); acc[0][1] = fmaf(a0, bv.y, acc[0][1]);
            acc[0][2] = fmaf(a0, bv.z, acc[0][2]); acc[0][3] = fmaf(a0, bv.w, acc[0][3]);
            acc[1][0] = fmaf(a1, bv.x, acc[1][0]); acc[1][1] = fmaf(a1, bv.y, acc[1][1]);
            acc[1][2] = fmaf(a1, bv.z, acc[1][2]); acc[1][3] = fmaf(a1, bv.w, acc[1][3]);
        }
    }
#pragma unroll
    for (int r = 0; r < 2; r++)
#pragma unroll
        for (int c = 0; c < 4; c++)
            g_qpart[(ks * NB + ty * 2 + r) * TKD + n0 + tx * 4 + c] = acc[r][c];
}

__global__ void reduce_q() {
    int idx = blockIdx.x * 256 + threadIdx.x;
    if (idx >= NB * TKD) return;
    float s = 0.f;
#pragma unroll
    for (int z = 0; z < KSLICES; z++) s += g_qpart[z * NB * TKD + idx];
    g_q[idx] = s;
}

// ======================= p vectors =======================
__global__ __launch_bounds__(256) void p_kernel(const float* __restrict__ wk) {
    int h = blockIdx.x;
    int j0 = blockIdx.y * 256;
    __shared__ float qs[32 * 64];
    __shared__ float ws[256 * 68];
    int t = threadIdx.x;
    for (int idx = t; idx < 512; idx += 256) {
        int b = idx >> 4, d4 = (idx & 15) * 4;
        *(float4*)&qs[b * 64 + d4] = *(const float4*)&g_q[b * TKD + h * DKH + d4];
    }
    for (int idx = t; idx < 256 * 16; idx += 256) {
        int row = idx >> 4, c4 = (idx & 15) * 4;
        *(float4*)&ws[row * 68 + c4] = *(const float4*)&wk[(j0 + row) * TKD + h * DKH + c4];
    }
    __syncthreads();
    float4 wr[16];
#pragma unroll
    for (int d4 = 0; d4 < 16; d4++) wr[d4] = *(const float4*)&ws[t * 68 + d4 * 4];
    int j = j0 + t;
    for (int b = 0; b < 32; b++) {
        float a = 0.f;
#pragma unroll
        for (int d4 = 0; d4 < 16; d4++) {
            float4 q4 = *(const float4*)&qs[b * 64 + d4 * 4];
            a = fmaf(wr[d4].x, q4.x, a);
            a = fmaf(wr[d4].y, q4.y, a);
            a = fmaf(wr[d4].z, q4.z, a);
            a = fmaf(wr[d4].w, q4.w, a);
        }
        g_p[(b * NHD + h) * QKIN + j] = a;
    }
}

// ======================= logits stage A: partial dots =======================
// grid (32 b, 4 jc), 256 threads; warp w = head h. smem: ka chunk [8][2048].
__global__ __launch_bounds__(256) void logits_part() {
    extern __shared__ float ska[];       // 8 * 2048
    int b = blockIdx.x, jc = blockIdx.y;
    int t = threadIdx.x;
    int h = t >> 5, lane = t & 31;
    for (int idx = t; idx < 4096; idx += 256) {
        int s = idx >> 9, j4 = (idx & 511) * 4;
        *(float4*)&ska[s * 2048 + j4] =
            *(const float4*)&g_ka[(b * 8 + s) * QKIN + jc * 2048 + j4];
    }
    __syncthreads();
    const float* pp = g_p + (b * NHD + h) * QKIN + jc * 2048;
    float acc[8] = {};
    for (int j = lane * 4; j < 2048; j += 128) {
        float4 pv = *(const float4*)&pp[j];
#pragma unroll
        for (int s = 0; s < 8; s++) {
            float4 kv = *(const float4*)&ska[s * 2048 + j];
            acc[s] = fmaf(kv.x, pv.x, acc[s]);
            acc[s] = fmaf(kv.y, pv.y, acc[s]);
            acc[s] = fmaf(kv.z, pv.z, acc[s]);
            acc[s] = fmaf(kv.w, pv.w, acc[s]);
        }
    }
#pragma unroll
    for (int s = 0; s < 8; s++)
#pragma unroll
        for (int off = 16; off; off >>= 1) acc[s] += __shfl_xor_sync(0xffffffffu, acc[s], off);
    if (lane == 0) {
#pragma unroll
        for (int s = 0; s < 8; s++) g_lgp[((b * 4 + jc) * 8 + h) * 8 + s] = acc[s];
    }
}

// ======================= logits stage B: rel-emb + softmax =======================
__global__ void wgt_kernel(const float* __restrict__ tk) {
    int b = blockIdx.x;
    int t = threadIdx.x;          // 64 threads: t = h*8+s
    int h = t >> 3, s = t & 7;
    float d = 0.f;
#pragma unroll
    for (int jc = 0; jc < 4; jc++) d += g_lgp[((b * 4 + jc) * 8 + h) * 8 + s];
    int r = c_ridx[s];
    float relv = 0.f;
    const float* qv = &g_q[b * TKD + h * DKH];
    const float* tkr = &tk[r * DKH];
#pragma unroll
    for (int k = 0; k < DKH; k++) relv = fmaf(qv[k], tkr[k], relv);
    float lg = (d + relv) * 0.125f;
    float m = lg;
#pragma unroll
    for (int off = 4; off; off >>= 1) m = fmaxf(m, __shfl_xor_sync(0xffffffffu, m, off, 8));
    float e = expf(lg - m);
    float sum = e;
#pragma unroll
    for (int off = 4; off; off >>= 1) sum += __shfl_xor_sync(0xffffffffu, sum, off, 8);
    g_wgt[b * 64 + t] = e / sum;
}

// ======================= weight fragment packer =======================
__global__ void wtrans_kernel(const float* __restrict__ cvw, const float* __restrict__ cow) {
    int t = blockIdx.x * 256 + threadIdx.x;
    if (t < 9 * 16 * 16 * 32) {
        int lane = t & 31, k = (t >> 5) & 15, nt = (t >> 9) & 15, tap = t >> 13;
        int o = nt * 8 + (lane >> 2);
        int cin = k * 8 + (lane & 3);
        float b0 = cvw[(tap * 128 + cin) * 128 + o];
        float b1 = cvw[(tap * 128 + cin + 4) * 128 + o];
        g_wBv[t] = make_float2(tf32r(b0), tf32r(b1));
    } else {
        int e = t - 9 * 16 * 16 * 32;
        if (e < 9 * 8 * 16 * 32) {
            int lane = e & 31, k = (e >> 5) & 15, nt = (e >> 9) & 7, tap = e >> 12;
            int o = nt * 8 + (lane >> 2);
            int cin = k * 8 + (lane & 3);
            float b0 = cow[(tap * 128 + cin) * 64 + o];
            float b1 = cow[(tap * 128 + cin + 4) * 64 + o];
            g_wBo[e] = make_float2(tf32r(b0), tf32r(b1));
        }
    }
}

// smem: s_w 16384 | s_wgt 8 | s_in 204*132
#define CV_SMEM_BYTES ((16392 + 204 * 132) * 4)

// ======================= conv_v =======================
__global__ __launch_bounds__(256, 1) void conv_v_kernel(
    const float* __restrict__ v_ant, const float* __restrict__ cvb,
    const float* __restrict__ tv) {
    int h = blockIdx.x, b = blockIdx.y;
    extern __shared__ float sm[];
    float* s_w   = sm;
    float* s_wgt = sm + 16384;
    float* s_in  = sm + 16392;
    int t = threadIdx.x;
    int wid = t >> 5, lane = t & 31;
    if (t < 8) s_wgt[t] = g_wgt[b * 64 + h * 8 + t];
    __syncthreads();

    for (int e = t; e < 6 * 34 * 32; e += 256) {
        int c4 = e & 31;
        int ci = (e >> 5) % 34;
        int ri = e / (34 * 32);
        int gr = h * 4 - 1 + ri;
        int gc = ci - 1;
        float ax = 0.f, ay = 0.f, az = 0.f, aw = 0.f;
        if (gr >= 0 && gr < 32 && gc >= 0 && gc < 32) {
            const float4* vp = (const float4*)v_ant;
            int base = (b * 8 * 1024 + gr * 32 + gc) * 32 + c4;
#pragma unroll
            for (int s = 0; s < 8; s++) {
                float4 vv = vp[base + s * 32768];
                float w = s_wgt[s];
                ax = fmaf(w, vv.x, ax); ay = fmaf(w, vv.y, ay);
                az = fmaf(w, vv.z, az); aw = fmaf(w, vv.w, aw);
            }
        }
        *(float4*)&s_in[(ri * 34 + ci) * 132 + c4 * 4] =
            make_float4(tf32r(ax), tf32r(ay), tf32r(az), tf32r(aw));
    }

    int mw = wid >> 1, nw = wid & 1;
    float4 acc[2][8];
#pragma unroll
    for (int m = 0; m < 2; m++)
#pragma unroll
        for (int nt = 0; nt < 8; nt++) acc[m][nt] = make_float4(0.f, 0.f, 0.f, 0.f);

    for (int tap = 0; tap < 9; tap++) {
        __syncthreads();
        const float4* srcw = (const float4*)(g_wBv + tap * 8192);
        float4* dw = (float4*)s_w;
        for (int e = t; e < 4096; e += 256) dw[e] = srcw[e];
        __syncthreads();
        int dy = tap / 3 - 1, dx = tap % 3 - 1;
        const float* ab = s_in + ((mw + 1 + dy) * 34 + 1 + dx) * 132;
        const float2* s_w2 = (const float2*)s_w;
#pragma unroll
        for (int k = 0; k < 16; k++) {
            int cin = k * 8 + (lane & 3);
            u32 a[2][4];
#pragma unroll
            for (int m = 0; m < 2; m++) {
                int c = m * 16 + (lane >> 2);
                a[m][0] = __float_as_uint(ab[c * 132 + cin]);
                a[m][1] = __float_as_uint(ab[(c + 8) * 132 + cin]);
                a[m][2] = __float_as_uint(ab[c * 132 + cin + 4]);
                a[m][3] = __float_as_uint(ab[(c + 8) * 132 + cin + 4]);
            }
#pragma unroll
            for (int nt = 0; nt < 8; nt++) {
                float2 bv = s_w2[((nw * 8 + nt) * 16 + k) * 32 + lane];
                mma_tf32(acc[0][nt], a[0], bv);
                mma_tf32(acc[1][nt], a[1], bv);
            }
        }
    }

    float W0 = s_wgt[0] + s_wgt[1] + s_wgt[2] + s_wgt[3] + s_wgt[4];
    float w5 = s_wgt[5], w6 = s_wgt[6], w7 = s_wgt[7];
    const float2* tv2 = (const float2*)tv;
#pragma unroll
    for (int m = 0; m < 2; m++) {
#pragma unroll
        for (int half = 0; half < 2; half++) {
            int p = mw * 32 + m * 16 + (lane >> 2) + half * 8;
            int gr = h * 4 + (p >> 5), gc = p & 31;
            float* dst = &g_x[(b * 1024 + gr * 32 + gc) * 128];
#pragma unroll
            for (int nt = 0; nt < 8; nt++) {
                int o = nw * 64 + nt * 8 + (lane & 3) * 2;
                int ti = p * 64 + (o >> 1);
                float2 z0 = tv2[ti];
                float2 z1 = tv2[8192 + ti];
                float2 z2 = tv2[16384 + ti];
                float2 z3 = tv2[24576 + ti];
                float2 bias = *(const float2*)&cvb[o];
                float ax = half ? acc[m][nt].z : acc[m][nt].x;
                float ay = half ? acc[m][nt].w : acc[m][nt].y;
                float2 r;
                r.x = ax + bias.x + W0 * z0.x + w5 * z1.x + w6 * z2.x + w7 * z3.x;
                r.y = ay + bias.y + W0 * z0.y + w5 * z1.y + w6 * z2.y + w7 * z3.y;
                *(float2*)&dst[o] = r;
            }
        }
    }
}

// smem: s_w 8192 | s_in 204*132
#define CO_SMEM_BYTES ((8192 + 204 * 132) * 4)

// ======================= conv_o =======================
__global__ __launch_bounds__(256, 1) void conv_o_kernel(
    const float* __restrict__ cob, float* __restrict__ out) {
    int rb = blockIdx.x, b = blockIdx.y;
    extern __shared__ float sm[];
    float* s_w  = sm;
    float* s_in = sm + 8192;
    int t = threadIdx.x;
    int wid = t >> 5, lane = t & 31;

    for (int e = t; e < 6 * 34 * 32; e += 256) {
        int c4 = e & 31;
        int ci = (e >> 5) % 34;
        int ri = e / (34 * 32);
        int gr = rb * 4 - 1 + ri, gc = ci - 1;
        float4 v = make_float4(0.f, 0.f, 0.f, 0.f);
        if (gr >= 0 && gr < 32 && gc >= 0 && gc < 32) {
            v = *(const float4*)&g_x[(b * 1024 + gr * 32 + gc) * 128 + c4 * 4];
            v = make_float4(tf32r(v.x), tf32r(v.y), tf32r(v.z), tf32r(v.w));
        }
        *(float4*)&s_in[(ri * 34 + ci) * 132 + c4 * 4] = v;
    }

    int mw = wid >> 1, nw = wid & 1;
    float4 acc[2][4];
#pragma unroll
    for (int m = 0; m < 2; m++)
#pragma unroll
        for (int nt = 0; nt < 4; nt++) acc[m][nt] = make_float4(0.f, 0.f, 0.f, 0.f);

    for (int tap = 0; tap < 9; tap++) {
        __syncthreads();
        const float4* srcw = (const float4*)(g_wBo + tap * 4096);
        float4* dw = (float4*)s_w;
        for (int e = t; e < 2048; e += 256) dw[e] = srcw[e];
        __syncthreads();
        int dy = tap / 3 - 1, dx = tap % 3 - 1;
        const float* ab = s_in + ((mw + 1 + dy) * 34 + 1 + dx) * 132;
        const float2* s_w2 = (const float2*)s_w;
#pragma unroll
        for (int k = 0; k < 16; k++) {
            int cin = k * 8 + (lane & 3);
            u32 a[2][4];
#pragma unroll
            for (int m = 0; m < 2; m++) {
                int c = m * 16 + (lane >> 2);
                a[m][0] = __float_as_uint(ab[c * 132 + cin]);
                a[m][1] = __float_as_uint(ab[(c + 8) * 132 + cin]);
                a[m][2] = __float_as_uint(ab[c * 132 + cin + 4]);
                a[m][3] = __float_as_uint(ab[(c + 8) * 132 + cin + 4]);
            }
#pragma unroll
            for (int nt = 0; nt < 4; nt++) {
                float2 bv = s_w2[((nw * 4 + nt) * 16 + k) * 32 + lane];
                mma_tf32(acc[0][nt], a[0], bv);
                mma_tf32(acc[1][nt], a[1], bv);
            }
        }
    }

#pragma unroll
    for (int m = 0; m < 2; m++) {
#pragma unroll
        for (int half = 0; half < 2; half++) {
            int p = mw * 32 + m * 16 + (lane >> 2) + half * 8;
            int gr = rb * 4 + (p >> 5), gc = p & 31;
            float* dst = &out[(b * 1024 + gr * 32 + gc) * 64];
#pragma unroll
            for (int nt = 0; nt < 4; nt++) {
                int o = nw * 32 + nt * 8 + (lane & 3) * 2;
                float2 bias = *(const float2*)&cob[o];
                float ax = half ? acc[m][nt].z : acc[m][nt].x;
                float ay = half ? acc[m][nt].w : acc[m][nt].y;
                float2 r;
                r.x = ax + bias.x;
                r.y = ay + bias.y;
                *(float2*)&dst[o] = r;
            }
        }
    }
}

extern "C" void kernel_launch(void* const* d_in, const int* in_sizes, int n_in,
                              void* d_out, int out_size) {
    const float* inputs = (const float*)d_in[0];
    const float* k_ant  = (const float*)d_in[1];
    const float* v_ant  = (const float*)d_in[2];
    const float* w_q    = (const float*)d_in[3];
    const float* w_k    = (const float*)d_in[4];
    const float* cvw    = (const float*)d_in[5];
    const float* cvb    = (const float*)d_in[6];
    const float* cow    = (const float*)d_in[7];
    const float* cob    = (const float*)d_in[8];
    const float* tk     = (const float*)d_in[9];
    const float* tv     = (const float*)d_in[10];
    float* out = (float*)d_out;

    static bool s_init = false;
    static cudaStream_t s1, s2;
    static cudaEvent_t ev0, ev1, ev2;
    if (!s_init) {
        cudaStreamCreateWithFlags(&s1, cudaStreamNonBlocking);
        cudaStreamCreateWithFlags(&s2, cudaStreamNonBlocking);
        cudaEventCreateWithFlags(&ev0, cudaEventDisableTiming);
        cudaEventCreateWithFlags(&ev1, cudaEventDisableTiming);
        cudaEventCreateWithFlags(&ev2, cudaEventDisableTiming);
        cudaFuncSetAttribute(conv_v_kernel, cudaFuncAttributeMaxDynamicSharedMemorySize, CV_SMEM_BYTES);
        cudaFuncSetAttribute(conv_o_kernel, cudaFuncAttributeMaxDynamicSharedMemorySize, CO_SMEM_BYTES);
        cudaFuncSetAttribute(logits_part, cudaFuncAttributeMaxDynamicSharedMemorySize, 8 * 2048 * 4);
        s_init = true;
    }

    // resolve the stream this call is (possibly) being captured on
    cudaStream_t origin = (cudaStream_t)0;
    cudaStreamCaptureStatus cs = cudaStreamCaptureStatusNone;
    cudaStreamIsCapturing(cudaStreamPerThread, &cs);
    if (cs == cudaStreamCaptureStatusActive) {
        origin = cudaStreamPerThread;
    } else {
        cudaStreamIsCapturing(cudaStreamLegacy, &cs);
        if (cs == cudaStreamCaptureStatusActive) origin = cudaStreamLegacy;
    }

    // fork side branches
    cudaEventRecord(ev0, origin);
    cudaStreamWaitEvent(s1, ev0, 0);
    cudaStreamWaitEvent(s2, ev0, 0);

    // branch 1: pool of k_antecedent (big, independent)
    pool_kernel<<<(NB * NS * 2048 + 255) / 256, 256, 0, s1>>>(k_ant, NB * NS, 1);
    cudaEventRecord(ev1, s1);

    // branch 2: conv weight fragment packing
    wtrans_kernel<<<(9 * 16 * 16 * 32 + 9 * 8 * 16 * 32 + 255) / 256, 256, 0, s2>>>(cvw, cow);
    cudaEventRecord(ev2, s2);

    // main chain: q path
    pool_kernel<<<(NB * 2048 + 255) / 256, 256, 0, origin>>>(inputs, NB, 0);
    gemm_splitk_q<<<dim3(8, KSLICES), 256, 0, origin>>>(w_q);
    reduce_q<<<(NB * TKD + 255) / 256, 256, 0, origin>>>();
    p_kernel<<<dim3(NHD, 32), 256, 0, origin>>>(w_k);

    // join pool_k, then logits + softmax
    cudaStreamWaitEvent(origin, ev1, 0);
    logits_part<<<dim3(NB, 4), 256, 8 * 2048 * 4, origin>>>();
    wgt_kernel<<<NB, 64, 0, origin>>>(tk);

    // join wtrans, then convs
    cudaStreamWaitEvent(origin, ev2, 0);
    conv_v_kernel<<<dim3(NHD, NB), 256, CV_SMEM_BYTES, origin>>>(v_ant, cvb, tv);
    conv_o_kernel<<<dim3(8, NB), 256, CO_SMEM_BYTES, origin>>>(cob, out);
}

// round 6
// speedup vs baseline: 3.2379x; 1.0155x over previous
#include <cuda_runtime.h>
#include <cstdint>

#define NB 32
#define NS 8
#define NHD 8
#define QKIN 8192
#define TKD 512
#define DKH 64
#define KSLICES 64
#define KSLEN 128

typedef unsigned long long u64;
typedef unsigned int u32;

// ---- scratch (static __device__ globals; no allocations) ----
__device__ float g_qa[NB * QKIN];
__device__ float g_ka[NB * NS * QKIN];
__device__ float g_qpart[KSLICES * NB * TKD];
__device__ float g_q[NB * TKD];
__device__ float g_p[NB * NHD * QKIN];
__device__ float g_lgp[NB * 8 * 64];         // logits partials [b][jc][h*8+s]
__device__ float g_wgt[NB * NHD * NS];
__device__ float g_x[NB * 1024 * 128];
__device__ float2 g_wBv[9 * 16 * 16 * 32];
__device__ float2 g_wBo[9 * 8 * 16 * 32];

__constant__ int c_ridx[8] = {0, 0, 0, 0, 0, 1, 2, 3};

__device__ __forceinline__ float tf32r(float x) {
    float y; asm("cvt.rna.tf32.f32 %0, %1;" : "=f"(y) : "f"(x)); return y;
}

__device__ __forceinline__ void mma_tf32(float4& d, const u32* a, float2 b) {
    asm volatile("mma.sync.aligned.m16n8k8.row.col.f32.tf32.tf32.f32 "
        "{%0,%1,%2,%3}, {%4,%5,%6,%7}, {%8,%9}, {%0,%1,%2,%3};"
        : "+f"(d.x), "+f"(d.y), "+f"(d.z), "+f"(d.w)
        : "r"(a[0]), "r"(a[1]), "r"(a[2]), "r"(a[3]),
          "r"(__float_as_uint(b.x)), "r"(__float_as_uint(b.y)));
}

// ======================= pool =======================
__global__ void pool_kernel(const float* __restrict__ in, int nImg, int which) {
    float* out = which ? g_ka : g_qa;
    int idx = blockIdx.x * 256 + threadIdx.x;
    if (idx >= nImg * 2048) return;
    int c4 = idx & 31;
    int pw = (idx >> 5) & 7;
    int ph = (idx >> 8) & 7;
    int img = idx >> 11;
    const float4* p4 = (const float4*)in;
    float sx = 0.f, sy = 0.f, sz = 0.f, sw = 0.f;
#pragma unroll
    for (int i = 0; i < 4; i++)
#pragma unroll
        for (int j = 0; j < 4; j++) {
            float4 v = p4[((img * 32 + ph * 4 + i) * 32 + pw * 4 + j) * 32 + c4];
            sx += v.x; sy += v.y; sz += v.z; sw += v.w;
        }
    ((float4*)out)[idx] = make_float4(sx * 0.0625f, sy * 0.0625f, sz * 0.0625f, sw * 0.0625f);
}

// ======================= q GEMM (split-K, pipelined) =======================
__global__ __launch_bounds__(256, 2) void gemm_splitk_q(const float* __restrict__ Wm) {
    __shared__ float As[32][36];
    __shared__ float Bs[32][68];
    int nt = blockIdx.x, ks = blockIdx.y;
    int t = threadIdx.x;
    int tx = t & 15, ty = t >> 4;
    float acc[2][4] = {};
    int n0 = nt * 64, kbase = ks * KSLEN;
    const float* A = g_qa;
    int ar = t >> 3, ac = (t & 7) * 4;
    int wr = t >> 4, wc = (t & 15) * 4;
    float4 aP  = *(const float4*)&A[ar * QKIN + kbase + ac];
    float4 wP0 = *(const float4*)&Wm[(kbase + wr) * TKD + n0 + wc];
    float4 wP1 = *(const float4*)&Wm[(kbase + wr + 16) * TKD + n0 + wc];
#pragma unroll
    for (int kt = 0; kt < KSLEN / 32; kt++) {
        __syncthreads();
        *(float4*)&As[ar][ac] = aP;
        *(float4*)&Bs[wr][wc] = wP0;
        *(float4*)&Bs[wr + 16][wc] = wP1;
        __syncthreads();
        if (kt + 1 < KSLEN / 32) {
            int k0 = kbase + (kt + 1) * 32;
            aP  = *(const float4*)&A[ar * QKIN + k0 + ac];
            wP0 = *(const float4*)&Wm[(k0 + wr) * TKD + n0 + wc];
            wP1 = *(const float4*)&Wm[(k0 + wr + 16) * TKD + n0 + wc];
        }
#pragma unroll
        for (int k = 0; k < 32; k++) {
            float a0 = As[ty * 2][k], a1 = As[ty * 2 + 1][k];
            float4 bv = *(const float4*)&Bs[k][tx * 4];
            acc[0][0] = fmaf(a0, bv.x, acc[0][0]); acc[0][1] = fmaf(a0, bv.y, acc[0][1]);
            acc[0][2] = fmaf(a0, bv.z, acc[0][2]); acc[0][3] = fmaf(a0, bv.w, acc[0][3]);
            acc[1][0] = fmaf(a1, bv.x, acc[1][0]); acc[1][1] = fmaf(a1, bv.y, acc[1][1]);
            acc[1][2] = fmaf(a1, bv.z, acc[1][2]); acc[1][3] = fmaf(a1, bv.w, acc[1][3]);
        }
    }
#pragma unroll
    for (int r = 0; r < 2; r++)
#pragma unroll
        for (int c = 0; c < 4; c++)
            g_qpart[(ks * NB + ty * 2 + r) * TKD + n0 + tx * 4 + c] = acc[r][c];
}

__global__ void reduce_q() {
    int idx = blockIdx.x * 256 + threadIdx.x;
    if (idx >= NB * TKD) return;
    float s = 0.f;
#pragma unroll
    for (int z = 0; z < KSLICES; z++) s += g_qpart[z * NB * TKD + idx];
    g_q[idx] = s;
}

// ======================= p vectors (b-split for 2x parallelism) =======================
__global__ __launch_bounds__(256) void p_kernel(const float* __restrict__ wk) {
    int h = blockIdx.x;
    int j0 = blockIdx.y * 256;
    int boff = blockIdx.z * 16;
    __shared__ float qs[16 * 64];
    __shared__ float ws[256 * 68];
    int t = threadIdx.x;
    if (t < 256) {
        int b = t >> 4, d4 = (t & 15) * 4;
        *(float4*)&qs[b * 64 + d4] = *(const float4*)&g_q[(boff + b) * TKD + h * DKH + d4];
    }
    for (int idx = t; idx < 256 * 16; idx += 256) {
        int row = idx >> 4, c4 = (idx & 15) * 4;
        *(float4*)&ws[row * 68 + c4] = *(const float4*)&wk[(j0 + row) * TKD + h * DKH + c4];
    }
    __syncthreads();
    float4 wr[16];
#pragma unroll
    for (int d4 = 0; d4 < 16; d4++) wr[d4] = *(const float4*)&ws[t * 68 + d4 * 4];
    int j = j0 + t;
    for (int bl = 0; bl < 16; bl++) {
        float a = 0.f;
#pragma unroll
        for (int d4 = 0; d4 < 16; d4++) {
            float4 q4 = *(const float4*)&qs[bl * 64 + d4 * 4];
            a = fmaf(wr[d4].x, q4.x, a);
            a = fmaf(wr[d4].y, q4.y, a);
            a = fmaf(wr[d4].z, q4.z, a);
            a = fmaf(wr[d4].w, q4.w, a);
        }
        g_p[((boff + bl) * NHD + h) * QKIN + j] = a;
    }
}

// ======================= logits stage A: partial dots (8 j-chunks) =======================
__global__ __launch_bounds__(256) void logits_part() {
    __shared__ float ska[8 * 1024];
    int b = blockIdx.x, jc = blockIdx.y;
    int t = threadIdx.x;
    int h = t >> 5, lane = t & 31;
    for (int idx = t; idx < 2048; idx += 256) {
        int s = idx >> 8, j4 = (idx & 255) * 4;
        *(float4*)&ska[s * 1024 + j4] =
            *(const float4*)&g_ka[(b * 8 + s) * QKIN + jc * 1024 + j4];
    }
    __syncthreads();
    const float* pp = g_p + (b * NHD + h) * QKIN + jc * 1024;
    float acc[8] = {};
#pragma unroll
    for (int jj = 0; jj < 8; jj++) {
        int j = lane * 4 + jj * 128;
        float4 pv = *(const float4*)&pp[j];
#pragma unroll
        for (int s = 0; s < 8; s++) {
            float4 kv = *(const float4*)&ska[s * 1024 + j];
            acc[s] = fmaf(kv.x, pv.x, acc[s]);
            acc[s] = fmaf(kv.y, pv.y, acc[s]);
            acc[s] = fmaf(kv.z, pv.z, acc[s]);
            acc[s] = fmaf(kv.w, pv.w, acc[s]);
        }
    }
#pragma unroll
    for (int s = 0; s < 8; s++)
#pragma unroll
        for (int off = 16; off; off >>= 1) acc[s] += __shfl_xor_sync(0xffffffffu, acc[s], off);
    if (lane == 0) {
#pragma unroll
        for (int s = 0; s < 8; s++) g_lgp[((b * 8 + jc) * 8 + h) * 8 + s] = acc[s];
    }
}

// ======================= logits stage B: rel-emb + softmax =======================
__global__ void wgt_kernel(const float* __restrict__ tk) {
    int b = blockIdx.x;
    int t = threadIdx.x;          // 64 threads: t = h*8+s
    int h = t >> 3, s = t & 7;
    float d = 0.f;
#pragma unroll
    for (int jc = 0; jc < 8; jc++) d += g_lgp[((b * 8 + jc) * 8 + h) * 8 + s];
    int r = c_ridx[s];
    float relv = 0.f;
    const float* qv = &g_q[b * TKD + h * DKH];
    const float* tkr = &tk[r * DKH];
#pragma unroll
    for (int k = 0; k < DKH; k++) relv = fmaf(qv[k], tkr[k], relv);
    float lg = (d + relv) * 0.125f;
    float m = lg;
#pragma unroll
    for (int off = 4; off; off >>= 1) m = fmaxf(m, __shfl_xor_sync(0xffffffffu, m, off, 8));
    float e = expf(lg - m);
    float sum = e;
#pragma unroll
    for (int off = 4; off; off >>= 1) sum += __shfl_xor_sync(0xffffffffu, sum, off, 8);
    g_wgt[b * 64 + t] = e / sum;
}

// ======================= weight fragment packer =======================
__global__ void wtrans_kernel(const float* __restrict__ cvw, const float* __restrict__ cow) {
    int t = blockIdx.x * 256 + threadIdx.x;
    if (t < 9 * 16 * 16 * 32) {
        int lane = t & 31, k = (t >> 5) & 15, nt = (t >> 9) & 15, tap = t >> 13;
        int o = nt * 8 + (lane >> 2);
        int cin = k * 8 + (lane & 3);
        float b0 = cvw[(tap * 128 + cin) * 128 + o];
        float b1 = cvw[(tap * 128 + cin + 4) * 128 + o];
        g_wBv[t] = make_float2(tf32r(b0), tf32r(b1));
    } else {
        int e = t - 9 * 16 * 16 * 32;
        if (e < 9 * 8 * 16 * 32) {
            int lane = e & 31, k = (e >> 5) & 15, nt = (e >> 9) & 7, tap = e >> 12;
            int o = nt * 8 + (lane >> 2);
            int cin = k * 8 + (lane & 3);
            float b0 = cow[(tap * 128 + cin) * 64 + o];
            float b1 = cow[(tap * 128 + cin + 4) * 64 + o];
            g_wBo[e] = make_float2(tf32r(b0), tf32r(b1));
        }
    }
}

// smem: s_w 16384 | s_wgt 8 | s_in 204*132
#define CV_SMEM_BYTES ((16392 + 204 * 132) * 4)

// ======================= conv_v =======================
__global__ __launch_bounds__(256, 1) void conv_v_kernel(
    const float* __restrict__ v_ant, const float* __restrict__ cvb,
    const float* __restrict__ tv, int boff) {
    int h = blockIdx.x, b = blockIdx.y + boff;
    extern __shared__ float sm[];
    float* s_w   = sm;
    float* s_wgt = sm + 16384;
    float* s_in  = sm + 16392;
    int t = threadIdx.x;
    int wid = t >> 5, lane = t & 31;
    if (t < 8) s_wgt[t] = g_wgt[b * 64 + h * 8 + t];
    __syncthreads();

    for (int e = t; e < 6 * 34 * 32; e += 256) {
        int c4 = e & 31;
        int ci = (e >> 5) % 34;
        int ri = e / (34 * 32);
        int gr = h * 4 - 1 + ri;
        int gc = ci - 1;
        float ax = 0.f, ay = 0.f, az = 0.f, aw = 0.f;
        if (gr >= 0 && gr < 32 && gc >= 0 && gc < 32) {
            const float4* vp = (const float4*)v_ant;
            int base = (b * 8 * 1024 + gr * 32 + gc) * 32 + c4;
#pragma unroll
            for (int s = 0; s < 8; s++) {
                float4 vv = vp[base + s * 32768];
                float w = s_wgt[s];
                ax = fmaf(w, vv.x, ax); ay = fmaf(w, vv.y, ay);
                az = fmaf(w, vv.z, az); aw = fmaf(w, vv.w, aw);
            }
        }
        *(float4*)&s_in[(ri * 34 + ci) * 132 + c4 * 4] =
            make_float4(tf32r(ax), tf32r(ay), tf32r(az), tf32r(aw));
    }

    int mw = wid >> 1, nw = wid & 1;
    float4 acc[2][8];
#pragma unroll
    for (int m = 0; m < 2; m++)
#pragma unroll
        for (int nt = 0; nt < 8; nt++) acc[m][nt] = make_float4(0.f, 0.f, 0.f, 0.f);

    for (int tap = 0; tap < 9; tap++) {
        __syncthreads();
        const float4* srcw = (const float4*)(g_wBv + tap * 8192);
        float4* dw = (float4*)s_w;
        for (int e = t; e < 4096; e += 256) dw[e] = srcw[e];
        __syncthreads();
        int dy = tap / 3 - 1, dx = tap % 3 - 1;
        const float* ab = s_in + ((mw + 1 + dy) * 34 + 1 + dx) * 132;
        const float2* s_w2 = (const float2*)s_w;
#pragma unroll
        for (int k = 0; k < 16; k++) {
            int cin = k * 8 + (lane & 3);
            u32 a[2][4];
#pragma unroll
            for (int m = 0; m < 2; m++) {
                int c = m * 16 + (lane >> 2);
                a[m][0] = __float_as_uint(ab[c * 132 + cin]);
                a[m][1] = __float_as_uint(ab[(c + 8) * 132 + cin]);
                a[m][2] = __float_as_uint(ab[c * 132 + cin + 4]);
                a[m][3] = __float_as_uint(ab[(c + 8) * 132 + cin + 4]);
            }
#pragma unroll
            for (int nt = 0; nt < 8; nt++) {
                float2 bv = s_w2[((nw * 8 + nt) * 16 + k) * 32 + lane];
                mma_tf32(acc[0][nt], a[0], bv);
                mma_tf32(acc[1][nt], a[1], bv);
            }
        }
    }

    float W0 = s_wgt[0] + s_wgt[1] + s_wgt[2] + s_wgt[3] + s_wgt[4];
    float w5 = s_wgt[5], w6 = s_wgt[6], w7 = s_wgt[7];
    const float2* tv2 = (const float2*)tv;
#pragma unroll
    for (int m = 0; m < 2; m++) {
#pragma unroll
        for (int half = 0; half < 2; half++) {
            int p = mw * 32 + m * 16 + (lane >> 2) + half * 8;
            int gr = h * 4 + (p >> 5), gc = p & 31;
            float* dst = &g_x[(b * 1024 + gr * 32 + gc) * 128];
#pragma unroll
            for (int nt = 0; nt < 8; nt++) {
                int o = nw * 64 + nt * 8 + (lane & 3) * 2;
                int ti = p * 64 + (o >> 1);
                float2 z0 = tv2[ti];
                float2 z1 = tv2[8192 + ti];
                float2 z2 = tv2[16384 + ti];
                float2 z3 = tv2[24576 + ti];
                float2 bias = *(const float2*)&cvb[o];
                float ax = half ? acc[m][nt].z : acc[m][nt].x;
                float ay = half ? acc[m][nt].w : acc[m][nt].y;
                float2 r;
                r.x = ax + bias.x + W0 * z0.x + w5 * z1.x + w6 * z2.x + w7 * z3.x;
                r.y = ay + bias.y + W0 * z0.y + w5 * z1.y + w6 * z2.y + w7 * z3.y;
                *(float2*)&dst[o] = r;
            }
        }
    }
}

// smem: s_w 8192 | s_in 204*132
#define CO_SMEM_BYTES ((8192 + 204 * 132) * 4)

// ======================= conv_o =======================
__global__ __launch_bounds__(256, 1) void conv_o_kernel(
    const float* __restrict__ cob, float* __restrict__ out, int boff) {
    int rb = blockIdx.x, b = blockIdx.y + boff;
    extern __shared__ float sm[];
    float* s_w  = sm;
    float* s_in = sm + 8192;
    int t = threadIdx.x;
    int wid = t >> 5, lane = t & 31;

    for (int e = t; e < 6 * 34 * 32; e += 256) {
        int c4 = e & 31;
        int ci = (e >> 5) % 34;
        int ri = e / (34 * 32);
        int gr = rb * 4 - 1 + ri, gc = ci - 1;
        float4 v = make_float4(0.f, 0.f, 0.f, 0.f);
        if (gr >= 0 && gr < 32 && gc >= 0 && gc < 32) {
            v = *(const float4*)&g_x[(b * 1024 + gr * 32 + gc) * 128 + c4 * 4];
            v = make_float4(tf32r(v.x), tf32r(v.y), tf32r(v.z), tf32r(v.w));
        }
        *(float4*)&s_in[(ri * 34 + ci) * 132 + c4 * 4] = v;
    }

    int mw = wid >> 1, nw = wid & 1;
    float4 acc[2][4];
#pragma unroll
    for (int m = 0; m < 2; m++)
#pragma unroll
        for (int nt = 0; nt < 4; nt++) acc[m][nt] = make_float4(0.f, 0.f, 0.f, 0.f);

    for (int tap = 0; tap < 9; tap++) {
        __syncthreads();
        const float4* srcw = (const float4*)(g_wBo + tap * 4096);
        float4* dw = (float4*)s_w;
        for (int e = t; e < 2048; e += 256) dw[e] = srcw[e];
        __syncthreads();
        int dy = tap / 3 - 1, dx = tap % 3 - 1;
        const float* ab = s_in + ((mw + 1 + dy) * 34 + 1 + dx) * 132;
        const float2* s_w2 = (const float2*)s_w;
#pragma unroll
        for (int k = 0; k < 16; k++) {
            int cin = k * 8 + (lane & 3);
            u32 a[2][4];
#pragma unroll
            for (int m = 0; m < 2; m++) {
                int c = m * 16 + (lane >> 2);
                a[m][0] = __float_as_uint(ab[c * 132 + cin]);
                a[m][1] = __float_as_uint(ab[(c + 8) * 132 + cin]);
                a[m][2] = __float_as_uint(ab[c * 132 + cin + 4]);
                a[m][3] = __float_as_uint(ab[(c + 8) * 132 + cin + 4]);
            }
#pragma unroll
            for (int nt = 0; nt < 4; nt++) {
                float2 bv = s_w2[((nw * 4 + nt) * 16 + k) * 32 + lane];
                mma_tf32(acc[0][nt], a[0], bv);
                mma_tf32(acc[1][nt], a[1], bv);
            }
        }
    }

#pragma unroll
    for (int m = 0; m < 2; m++) {
#pragma unroll
        for (int half = 0; half < 2; half++) {
            int p = mw * 32 + m * 16 + (lane >> 2) + half * 8;
            int gr = rb * 4 + (p >> 5), gc = p & 31;
            float* dst = &out[(b * 1024 + gr * 32 + gc) * 64];
#pragma unroll
            for (int nt = 0; nt < 4; nt++) {
                int o = nw * 32 + nt * 8 + (lane & 3) * 2;
                float2 bias = *(const float2*)&cob[o];
                float ax = half ? acc[m][nt].z : acc[m][nt].x;
                float ay = half ? acc[m][nt].w : acc[m][nt].y;
                float2 r;
                r.x = ax + bias.x;
                r.y = ay + bias.y;
                *(float2*)&dst[o] = r;
            }
        }
    }
}

extern "C" void kernel_launch(void* const* d_in, const int* in_sizes, int n_in,
                              void* d_out, int out_size) {
    const float* inputs = (const float*)d_in[0];
    const float* k_ant  = (const float*)d_in[1];
    const float* v_ant  = (const float*)d_in[2];
    const float* w_q    = (const float*)d_in[3];
    const float* w_k    = (const float*)d_in[4];
    const float* cvw    = (const float*)d_in[5];
    const float* cvb    = (const float*)d_in[6];
    const float* cow    = (const float*)d_in[7];
    const float* cob    = (const float*)d_in[8];
    const float* tk     = (const float*)d_in[9];
    const float* tv     = (const float*)d_in[10];
    float* out = (float*)d_out;

    static bool s_init = false;
    static cudaStream_t s1, s2;
    static cudaEvent_t ev0, ev1, ev2, evA, ev3;
    if (!s_init) {
        cudaStreamCreateWithFlags(&s1, cudaStreamNonBlocking);
        cudaStreamCreateWithFlags(&s2, cudaStreamNonBlocking);
        cudaEventCreateWithFlags(&ev0, cudaEventDisableTiming);
        cudaEventCreateWithFlags(&ev1, cudaEventDisableTiming);
        cudaEventCreateWithFlags(&ev2, cudaEventDisableTiming);
        cudaEventCreateWithFlags(&evA, cudaEventDisableTiming);
        cudaEventCreateWithFlags(&ev3, cudaEventDisableTiming);
        cudaFuncSetAttribute(conv_v_kernel, cudaFuncAttributeMaxDynamicSharedMemorySize, CV_SMEM_BYTES);
        cudaFuncSetAttribute(conv_o_kernel, cudaFuncAttributeMaxDynamicSharedMemorySize, CO_SMEM_BYTES);
        s_init = true;
    }

    cudaStream_t origin = (cudaStream_t)0;
    cudaStreamCaptureStatus cs = cudaStreamCaptureStatusNone;
    cudaStreamIsCapturing(cudaStreamPerThread, &cs);
    if (cs == cudaStreamCaptureStatusActive) {
        origin = cudaStreamPerThread;
    } else {
        cudaStreamIsCapturing(cudaStreamLegacy, &cs);
        if (cs == cudaStreamCaptureStatusActive) origin = cudaStreamLegacy;
    }

    // fork side branches
    cudaEventRecord(ev0, origin);
    cudaStreamWaitEvent(s1, ev0, 0);
    cudaStreamWaitEvent(s2, ev0, 0);

    // branch 1: pool of k_antecedent
    pool_kernel<<<(NB * NS * 2048 + 255) / 256, 256, 0, s1>>>(k_ant, NB * NS, 1);
    cudaEventRecord(ev1, s1);

    // branch 2: conv weight fragment packing
    wtrans_kernel<<<(9 * 16 * 16 * 32 + 9 * 8 * 16 * 32 + 255) / 256, 256, 0, s2>>>(cvw, cow);
    cudaEventRecord(ev2, s2);

    // main chain: q path
    pool_kernel<<<(NB * 2048 + 255) / 256, 256, 0, origin>>>(inputs, NB, 0);
    gemm_splitk_q<<<dim3(8, KSLICES), 256, 0, origin>>>(w_q);
    reduce_q<<<(NB * TKD + 255) / 256, 256, 0, origin>>>();
    p_kernel<<<dim3(NHD, 32, 2), 256, 0, origin>>>(w_k);

    // join pool_k, then logits + softmax
    cudaStreamWaitEvent(origin, ev1, 0);
    logits_part<<<dim3(NB, 8), 256, 0, origin>>>();
    wgt_kernel<<<NB, 64, 0, origin>>>(tk);

    // join wtrans, then convs pipelined over batch halves
    cudaStreamWaitEvent(origin, ev2, 0);
    conv_v_kernel<<<dim3(NHD, 16), 256, CV_SMEM_BYTES, origin>>>(v_ant, cvb, tv, 0);
    cudaEventRecord(evA, origin);

    // conv_o(half0) runs on s1 concurrently with conv_v(half1)
    cudaStreamWaitEvent(s1, evA, 0);
    cudaStreamWaitEvent(s1, ev2, 0);
    conv_o_kernel<<<dim3(8, 16), 256, CO_SMEM_BYTES, s1>>>(cob, out, 0);
    cudaEventRecord(ev3, s1);

    conv_v_kernel<<<dim3(NHD, 16), 256, CV_SMEM_BYTES, origin>>>(v_ant, cvb, tv, 16);
    cudaStreamWaitEvent(origin, ev3, 0);
    conv_o_kernel<<<dim3(8, 16), 256, CO_SMEM_BYTES, origin>>>(cob, out, 16);
}